// round 14
// baseline (speedup 1.0000x reference)
#include <cuda_runtime.h>
#include <cuda_fp16.h>
#include <cstdint>

#define TOK    8192
#define DMODEL 512
#define SQ     2048
#define NHEADS 8
#define HDIM   64
#define WIN    5

// ---------------------------------------------------------------------------
// Device scratch (half). Weights in [K][N] layout.
// ---------------------------------------------------------------------------
__device__ __half g_xh[(size_t)TOK * DMODEL];
__device__ __half g_h1[(size_t)TOK * 1024];
__device__ __half g_xm[(size_t)TOK * DMODEL];
__device__ __half g_q [(size_t)TOK * DMODEL];
__device__ __half g_k [(size_t)TOK * DMODEL];
__device__ __half g_vt[(size_t)4 * NHEADS * HDIM * SQ];  // [b*8+h][d][s]
__device__ __half g_o [(size_t)TOK * DMODEL];
__device__ __half g_w1h[(size_t)512 * 1024];
__device__ __half g_w2h[(size_t)1024 * 512];
__device__ __half g_wqh[(size_t)512 * 512];
__device__ __half g_wkh[(size_t)512 * 512];
__device__ __half g_wvh[(size_t)512 * 512];
__device__ __half g_woh[(size_t)512 * 512];

// ---------------------------------------------------------------------------
// helpers
// ---------------------------------------------------------------------------
__device__ __forceinline__ uint32_t smem_u32(const void* p) {
    uint32_t a;
    asm("{ .reg .u64 t; cvta.to.shared.u64 t, %1; cvt.u32.u64 %0, t; }"
        : "=r"(a) : "l"(p));
    return a;
}

#define CP_ASYNC16(dst_u32, src_ptr) \
    asm volatile("cp.async.cg.shared.global [%0], [%1], 16;" \
                 :: "r"(dst_u32), "l"(src_ptr) : "memory")
#define CP_COMMIT() asm volatile("cp.async.commit_group;" ::: "memory")
#define CP_WAIT(n)  asm volatile("cp.async.wait_group %0;" :: "n"(n) : "memory")

__device__ __forceinline__ void mma_f16(
    float& d0, float& d1, float& d2, float& d3,
    unsigned a0, unsigned a1, unsigned a2, unsigned a3,
    unsigned b0, unsigned b1)
{
    asm volatile(
        "mma.sync.aligned.m16n8k16.row.col.f32.f16.f16.f32 "
        "{%0,%1,%2,%3},{%4,%5,%6,%7},{%8,%9},{%0,%1,%2,%3};\n"
        : "+f"(d0), "+f"(d1), "+f"(d2), "+f"(d3)
        : "r"(a0), "r"(a1), "r"(a2), "r"(a3), "r"(b0), "r"(b1));
}

__device__ __forceinline__ void ldm_x4(
    unsigned& r0, unsigned& r1, unsigned& r2, unsigned& r3, uint32_t addr)
{
    asm volatile("ldmatrix.sync.aligned.m8n8.x4.shared.b16 {%0,%1,%2,%3}, [%4];"
        : "=r"(r0), "=r"(r1), "=r"(r2), "=r"(r3) : "r"(addr));
}

__device__ __forceinline__ void ldm_x4_t(
    unsigned& r0, unsigned& r1, unsigned& r2, unsigned& r3, uint32_t addr)
{
    asm volatile("ldmatrix.sync.aligned.m8n8.x4.trans.shared.b16 {%0,%1,%2,%3}, [%4];"
        : "=r"(r0), "=r"(r1), "=r"(r2), "=r"(r3) : "r"(addr));
}

__device__ __forceinline__ unsigned h2u(__half2 h) {
    return *(unsigned*)&h;
}

// ---------------------------------------------------------------------------
// Fused prep: fp32 -> half for x + 6 weights in ONE launch.
// ---------------------------------------------------------------------------
struct Prep {
    const float* src[7];
    __half* dst[7];
    unsigned cum[8];
};

__global__ __launch_bounds__(256) void prep_all(Prep p)
{
    const unsigned i = blockIdx.x * 256 + threadIdx.x;
    if (i >= p.cum[7]) return;
    int s = 0;
#pragma unroll
    for (int j = 1; j < 7; j++) s += (i >= p.cum[j]) ? 1 : 0;
    const unsigned off = i - p.cum[s];
    float4 v = ((const float4*)p.src[s])[off];
    __half2* d = (__half2*)(p.dst[s] + (size_t)off * 4);
    d[0] = __floats2half2_rn(v.x, v.y);
    d[1] = __floats2half2_rn(v.z, v.w);
}

// ---------------------------------------------------------------------------
// FP16 GEMM (round-12 config): BM=64, BN=128, BK=64; 128 threads, 4 warps,
// warp tile 32x64, 2-stage cp.async, single barrier per k-iter.
// ---------------------------------------------------------------------------
#define AP2 72     // A row stride in halves (64+8)
#define BPH 136    // B row stride in halves (128+8)
#define A_ST (64 * AP2 * 2)          // 9216 B per A stage
#define B_ST (64 * BPH * 2)          // 17408 B per B stage
#define GSMEM (2 * (A_ST + B_ST))    // 53248

template<int RELU, int OMODE>
__global__ void __launch_bounds__(128, 4) gemm_f16(
    const __half* __restrict__ A, const __half* __restrict__ W,
    const float* __restrict__ bias, void* __restrict__ Cv,
    int M, int N, int K)
{
    extern __shared__ __half smg[];
    const uint32_t aBase = smem_u32(smg);
    const uint32_t bBase = aBase + 2 * A_ST;

    const int tid  = threadIdx.x;
    const int warp = tid >> 5;
    const int lane = tid & 31;
    const int g    = lane >> 2;
    const int tg   = lane & 3;
    const int wm   = warp >> 1;
    const int wn   = warp & 1;
    const int m0   = blockIdx.y * 64;
    const int n0   = blockIdx.x * 128;

    float acc[2][8][4];
#pragma unroll
    for (int mi = 0; mi < 2; mi++)
#pragma unroll
        for (int nj = 0; nj < 8; nj++)
#pragma unroll
            for (int r = 0; r < 4; r++) acc[mi][nj][r] = 0.f;

    const int nt = K >> 6;

    auto issue = [&](int kt, int slot) {
        const int k0 = kt << 6;
        const uint32_t aOff = aBase + slot * A_ST;
        const uint32_t bOff = bBase + slot * B_ST;
#pragma unroll
        for (int t = 0; t < 4; t++) {
            const int ia = tid + t * 128;
            const int ra = ia >> 3, ca = ia & 7;
            CP_ASYNC16(aOff + (uint32_t)(ra * AP2 * 2 + ca * 16),
                       A + (size_t)(m0 + ra) * K + k0 + ca * 8);
        }
#pragma unroll
        for (int t = 0; t < 8; t++) {
            const int ib = tid + t * 128;
            const int rb = ib >> 4, cb = ib & 15;
            CP_ASYNC16(bOff + (uint32_t)(rb * BPH * 2 + cb * 16),
                       W + (size_t)(k0 + rb) * N + n0 + cb * 8);
        }
        CP_COMMIT();
    };

    issue(0, 0);

    for (int kt = 0; kt < nt; kt++) {
        const int slot = kt & 1;
        CP_WAIT(0);
        __syncthreads();
        if (kt + 1 < nt) issue(kt + 1, slot ^ 1);

        const uint32_t aB = aBase + slot * A_ST;
        const uint32_t bB = bBase + slot * B_ST;
        const int lrow = lane & 15;
        const int lcol = (lane >> 4) << 3;

#pragma unroll
        for (int ks = 0; ks < 4; ks++) {
            const int kb = ks * 16;
            unsigned a[2][4];
#pragma unroll
            for (int mi = 0; mi < 2; mi++) {
                const int row0 = wm * 32 + mi * 16;
                ldm_x4(a[mi][0], a[mi][1], a[mi][2], a[mi][3],
                       aB + (uint32_t)(((row0 + lrow) * AP2 + kb + lcol) * 2));
            }
            unsigned b[8][2];
#pragma unroll
            for (int njp = 0; njp < 4; njp++) {
                const int col0 = wn * 64 + njp * 16;
                ldm_x4_t(b[2 * njp][0], b[2 * njp][1],
                         b[2 * njp + 1][0], b[2 * njp + 1][1],
                         bB + (uint32_t)(((kb + lrow) * BPH + col0 + lcol) * 2));
            }
#pragma unroll
            for (int mi = 0; mi < 2; mi++)
#pragma unroll
                for (int nj = 0; nj < 8; nj++)
                    mma_f16(acc[mi][nj][0], acc[mi][nj][1],
                            acc[mi][nj][2], acc[mi][nj][3],
                            a[mi][0], a[mi][1], a[mi][2], a[mi][3],
                            b[nj][0], b[nj][1]);
        }
    }

    // Epilogue
#pragma unroll
    for (int mi = 0; mi < 2; mi++) {
        const int row = m0 + wm * 32 + mi * 16 + g;
#pragma unroll
        for (int nj = 0; nj < 8; nj++) {
            const int col = n0 + wn * 64 + nj * 8 + tg * 2;
            float2 bv = *(const float2*)(bias + col);
            float c0x = acc[mi][nj][0] + bv.x;
            float c0y = acc[mi][nj][1] + bv.y;
            float c1x = acc[mi][nj][2] + bv.x;
            float c1y = acc[mi][nj][3] + bv.y;
            if (RELU) {
                c0x = fmaxf(c0x, 0.f); c0y = fmaxf(c0y, 0.f);
                c1x = fmaxf(c1x, 0.f); c1y = fmaxf(c1y, 0.f);
            }
            if (OMODE == 0) {
                float* C = (float*)Cv;
                float2 u; u.x = c0x; u.y = c0y;
                float2 w; w.x = c1x; w.y = c1y;
                *(float2*)(C + (size_t)row * N + col)       = u;
                *(float2*)(C + (size_t)(row + 8) * N + col) = w;
            } else {
                __half* C = (__half*)Cv;
                *(__half2*)(C + (size_t)row * N + col)       = __floats2half2_rn(c0x, c0y);
                *(__half2*)(C + (size_t)(row + 8) * N + col) = __floats2half2_rn(c1x, c1y);
            }
        }
    }
}

// ---------------------------------------------------------------------------
// Fused QKV GEMM (round-12 config): BM=64, BK=64, N=1536 regions q/k/vt.
// ---------------------------------------------------------------------------
struct QKVp {
    const __half* w[3];
    const float*  b[3];
    __half* q; __half* k; __half* vt;
};

__global__ void __launch_bounds__(128, 4) gemm_qkv(
    const __half* __restrict__ A, QKVp p, int M, int K)
{
    extern __shared__ __half smg[];
    const uint32_t aBase = smem_u32(smg);
    const uint32_t bBase = aBase + 2 * A_ST;

    const int tid  = threadIdx.x;
    const int warp = tid >> 5;
    const int lane = tid & 31;
    const int g    = lane >> 2;
    const int tg   = lane & 3;
    const int wm   = warp >> 1;
    const int wn   = warp & 1;
    const int m0   = blockIdx.y * 64;
    const int n0g  = blockIdx.x * 128;
    const int reg  = n0g >> 9;
    const int n0   = n0g & 511;
    const __half* W = p.w[reg];
    const float* bias = p.b[reg];

    float acc[2][8][4];
#pragma unroll
    for (int mi = 0; mi < 2; mi++)
#pragma unroll
        for (int nj = 0; nj < 8; nj++)
#pragma unroll
            for (int r = 0; r < 4; r++) acc[mi][nj][r] = 0.f;

    const int nt = K >> 6;

    auto issue = [&](int kt, int slot) {
        const int k0 = kt << 6;
        const uint32_t aOff = aBase + slot * A_ST;
        const uint32_t bOff = bBase + slot * B_ST;
#pragma unroll
        for (int t = 0; t < 4; t++) {
            const int ia = tid + t * 128;
            const int ra = ia >> 3, ca = ia & 7;
            CP_ASYNC16(aOff + (uint32_t)(ra * AP2 * 2 + ca * 16),
                       A + (size_t)(m0 + ra) * K + k0 + ca * 8);
        }
#pragma unroll
        for (int t = 0; t < 8; t++) {
            const int ib = tid + t * 128;
            const int rb = ib >> 4, cb = ib & 15;
            CP_ASYNC16(bOff + (uint32_t)(rb * BPH * 2 + cb * 16),
                       W + (size_t)(k0 + rb) * 512 + n0 + cb * 8);
        }
        CP_COMMIT();
    };

    issue(0, 0);

    for (int kt = 0; kt < nt; kt++) {
        const int slot = kt & 1;
        CP_WAIT(0);
        __syncthreads();
        if (kt + 1 < nt) issue(kt + 1, slot ^ 1);

        const uint32_t aB = aBase + slot * A_ST;
        const uint32_t bB = bBase + slot * B_ST;
        const int lrow = lane & 15;
        const int lcol = (lane >> 4) << 3;

#pragma unroll
        for (int ks = 0; ks < 4; ks++) {
            const int kb = ks * 16;
            unsigned a[2][4];
#pragma unroll
            for (int mi = 0; mi < 2; mi++) {
                const int row0 = wm * 32 + mi * 16;
                ldm_x4(a[mi][0], a[mi][1], a[mi][2], a[mi][3],
                       aB + (uint32_t)(((row0 + lrow) * AP2 + kb + lcol) * 2));
            }
            unsigned b[8][2];
#pragma unroll
            for (int njp = 0; njp < 4; njp++) {
                const int col0 = wn * 64 + njp * 16;
                ldm_x4_t(b[2 * njp][0], b[2 * njp][1],
                         b[2 * njp + 1][0], b[2 * njp + 1][1],
                         bB + (uint32_t)(((kb + lrow) * BPH + col0 + lcol) * 2));
            }
#pragma unroll
            for (int mi = 0; mi < 2; mi++)
#pragma unroll
                for (int nj = 0; nj < 8; nj++)
                    mma_f16(acc[mi][nj][0], acc[mi][nj][1],
                            acc[mi][nj][2], acc[mi][nj][3],
                            a[mi][0], a[mi][1], a[mi][2], a[mi][3],
                            b[nj][0], b[nj][1]);
        }
    }

#pragma unroll
    for (int mi = 0; mi < 2; mi++) {
        const int row = m0 + wm * 32 + mi * 16 + g;
#pragma unroll
        for (int nj = 0; nj < 8; nj++) {
            const int coln = n0 + wn * 64 + nj * 8 + tg * 2;
            float2 bv = *(const float2*)(bias + coln);
            const float c0x = acc[mi][nj][0] + bv.x;
            const float c0y = acc[mi][nj][1] + bv.y;
            const float c1x = acc[mi][nj][2] + bv.x;
            const float c1y = acc[mi][nj][3] + bv.y;
            if (reg == 2) {
                __half* C = p.vt;
                const int b = row >> 11, s = row & 2047;
                const int h = coln >> 6, dd = coln & 63;
                const size_t base = (((size_t)(b * 8 + h) * 64 + dd) << 11);
                C[base + s]            = __float2half_rn(c0x);
                C[base + 2048 + s]     = __float2half_rn(c0y);
                C[base + s + 8]        = __float2half_rn(c1x);
                C[base + 2048 + s + 8] = __float2half_rn(c1y);
            } else {
                __half* C = (reg == 0) ? p.q : p.k;
                *(__half2*)(C + (size_t)row * DMODEL + coln)       = __floats2half2_rn(c0x, c0y);
                *(__half2*)(C + (size_t)(row + 8) * DMODEL + coln) = __floats2half2_rn(c1x, c1y);
            }
        }
    }
}

// ---------------------------------------------------------------------------
// FP16 flash attention v4: QTILE=128, 16 q-rows/warp (reg-slim -> 2 blocks/SM),
// register-resident P, cp.async K/V pipeline, exp2 softmax.
// ---------------------------------------------------------------------------
#define QP_STRIDE 72
#define QTILE 128
#define KVBUF (64 * QP_STRIDE)

__global__ void __launch_bounds__(256, 2) attn_f16(
    const __half* __restrict__ Qg, const __half* __restrict__ Kg,
    const __half* __restrict__ Vt, __half* __restrict__ Og)
{
    extern __shared__ __half smh[];
    __half (*QP)[QP_STRIDE] = (__half(*)[QP_STRIDE])smh;   // [128][72]
    __half* KsBase = smh + QTILE * QP_STRIDE;              // [2][64][72]
    __half* VsBase = KsBase + 2 * KVBUF;                   // [2][64][72]

    const int tid  = threadIdx.x;
    const int warp = tid >> 5;
    const int lane = tid & 31;
    const int g    = lane >> 2;
    const int tg   = lane & 3;
    const int bh   = blockIdx.y;
    const int b    = bh >> 3;
    const int h    = bh & 7;
    const int q0   = blockIdx.x * QTILE;
    const int wrow = warp * 16;          // 16 q-rows per warp

    const uint32_t qpB = smem_u32(&QP[0][0]);
    const uint32_t ksB = smem_u32(KsBase);
    const uint32_t vsB = smem_u32(VsBase);
    const int lr16 = lane & 15;
    const int lc16 = (lane >> 4) << 3;
    const int lr8  = (lane & 7) + ((lane >> 4) << 3);
    const int lc8  = ((lane >> 3) & 1) << 3;

    const __half* Qb  = Qg + (size_t)b * SQ * DMODEL + h * HDIM;
    const __half* Kb  = Kg + (size_t)b * SQ * DMODEL + h * HDIM;
    const __half* Vtb = Vt + (size_t)bh * HDIM * SQ;

    // Stage Q (128x64) scaled by 0.125*log2e: 1024 uint4 -> 4 per thread
    const __half2 sc = __float2half2_rn(0.125f * 1.4426950408889634f);
#pragma unroll
    for (int t = 0; t < 4; t++) {
        const int idx = tid + t * 256;
        const int r = idx >> 3, c = (idx & 7) * 8;
        uint4 v = *(const uint4*)(Qb + (size_t)(q0 + r) * DMODEL + c);
        __half2* pv = (__half2*)&v;
#pragma unroll
        for (int j = 0; j < 4; j++) pv[j] = __hmul2(pv[j], sc);
        *(uint4*)&QP[r][c] = v;
    }

    // Prologue: K/V tile 0
#pragma unroll
    for (int t = 0; t < 2; t++) {
        const int idx = tid + t * 256;
        const int r = idx >> 3, c = (idx & 7) * 8;
        CP_ASYNC16(ksB + (uint32_t)((r * QP_STRIDE + c) * 2),
                   Kb + (size_t)r * DMODEL + c);
        CP_ASYNC16(vsB + (uint32_t)((r * QP_STRIDE + c) * 2),
                   Vtb + (size_t)r * SQ + c);
    }
    CP_COMMIT();
    __syncthreads();

    // Q fragments: 4 k-steps x 4 regs (one 16-row m-tile)
    unsigned qf[4][4];
#pragma unroll
    for (int ks = 0; ks < 4; ks++) {
        const int kb = ks * 16;
        ldm_x4(qf[ks][0], qf[ks][1], qf[ks][2], qf[ks][3],
               qpB + (uint32_t)(((wrow + lr16) * QP_STRIDE + kb + lc16) * 2));
    }

    float oacc[8][4];
#pragma unroll
    for (int nj = 0; nj < 8; nj++)
#pragma unroll
        for (int r = 0; r < 4; r++) oacc[nj][r] = 0.f;
    float mrow[2] = { -1e30f, -1e30f };
    float lrow[2] = { 0.f, 0.f };

    const int NT = SQ / 64;
    for (int kt = 0; kt < NT; kt++) {
        const int k0 = kt * 64;
        const int buf = kt & 1;

        CP_WAIT(0);
        __syncthreads();

        if (kt + 1 < NT) {
            const int kn = (kt + 1) * 64;
            const uint32_t kOff = ksB + (buf ^ 1) * KVBUF * 2;
            const uint32_t vOff = vsB + (buf ^ 1) * KVBUF * 2;
#pragma unroll
            for (int t = 0; t < 2; t++) {
                const int idx = tid + t * 256;
                const int r = idx >> 3, c = (idx & 7) * 8;
                CP_ASYNC16(kOff + (uint32_t)((r * QP_STRIDE + c) * 2),
                           Kb + (size_t)(kn + r) * DMODEL + c);
                CP_ASYNC16(vOff + (uint32_t)((r * QP_STRIDE + c) * 2),
                           Vtb + (size_t)r * SQ + kn + c);
            }
            CP_COMMIT();
        }

        const uint32_t kB = ksB + buf * KVBUF * 2;
        const uint32_t vB = vsB + buf * KVBUF * 2;

        // S = Q @ K^T (16x64 per warp)
        float sfrag[8][4];
#pragma unroll
        for (int nj = 0; nj < 8; nj++)
#pragma unroll
            for (int r = 0; r < 4; r++) sfrag[nj][r] = 0.f;

#pragma unroll
        for (int ks = 0; ks < 4; ks++) {
            const int kb = ks * 16;
            unsigned bq[8][2];
#pragma unroll
            for (int njp = 0; njp < 4; njp++) {
                ldm_x4(bq[2 * njp][0], bq[2 * njp][1],
                       bq[2 * njp + 1][0], bq[2 * njp + 1][1],
                       kB + (uint32_t)(((njp * 16 + lr8) * QP_STRIDE + kb + lc8) * 2));
            }
#pragma unroll
            for (int nj = 0; nj < 8; nj++)
                mma_f16(sfrag[nj][0], sfrag[nj][1], sfrag[nj][2], sfrag[nj][3],
                        qf[ks][0], qf[ks][1], qf[ks][2], qf[ks][3],
                        bq[nj][0], bq[nj][1]);
        }

        // Inverse-band mask
        const bool need_mask = (k0 <= q0 + QTILE - 1 + WIN) && (k0 + 63 >= q0 - WIN);
        if (need_mask) {
            const int qr0 = q0 + wrow + g;
            const int qr1 = qr0 + 8;
#pragma unroll
            for (int nj = 0; nj < 8; nj++) {
                const int kc0 = k0 + nj * 8 + tg * 2;
                if ((unsigned)(qr0 - kc0     + WIN) <= 2 * WIN) sfrag[nj][0] = -1e9f;
                if ((unsigned)(qr0 - kc0 - 1 + WIN) <= 2 * WIN) sfrag[nj][1] = -1e9f;
                if ((unsigned)(qr1 - kc0     + WIN) <= 2 * WIN) sfrag[nj][2] = -1e9f;
                if ((unsigned)(qr1 - kc0 - 1 + WIN) <= 2 * WIN) sfrag[nj][3] = -1e9f;
            }
        }

        // Online softmax (exp2 domain); P packed into register A-fragments
        unsigned pf[8][2];
        {
            float tmax0 = -1e30f, tmax1 = -1e30f;
#pragma unroll
            for (int nj = 0; nj < 8; nj++) {
                tmax0 = fmaxf(tmax0, fmaxf(sfrag[nj][0], sfrag[nj][1]));
                tmax1 = fmaxf(tmax1, fmaxf(sfrag[nj][2], sfrag[nj][3]));
            }
#pragma unroll
            for (int off = 1; off <= 2; off <<= 1) {
                tmax0 = fmaxf(tmax0, __shfl_xor_sync(0xffffffffu, tmax0, off));
                tmax1 = fmaxf(tmax1, __shfl_xor_sync(0xffffffffu, tmax1, off));
            }
            const float mnew0 = fmaxf(mrow[0], tmax0);
            const float mnew1 = fmaxf(mrow[1], tmax1);
            const float alpha0 = exp2f(mrow[0] - mnew0);
            const float alpha1 = exp2f(mrow[1] - mnew1);

            float rs0 = 0.f, rs1 = 0.f;
#pragma unroll
            for (int nj = 0; nj < 8; nj++) {
                const float p0 = exp2f(sfrag[nj][0] - mnew0);
                const float p1 = exp2f(sfrag[nj][1] - mnew0);
                const float p2 = exp2f(sfrag[nj][2] - mnew1);
                const float p3 = exp2f(sfrag[nj][3] - mnew1);
                rs0 += p0 + p1;
                rs1 += p2 + p3;
                pf[nj][0] = h2u(__floats2half2_rn(p0, p1));
                pf[nj][1] = h2u(__floats2half2_rn(p2, p3));
            }
#pragma unroll
            for (int off = 1; off <= 2; off <<= 1) {
                rs0 += __shfl_xor_sync(0xffffffffu, rs0, off);
                rs1 += __shfl_xor_sync(0xffffffffu, rs1, off);
            }
            lrow[0] = lrow[0] * alpha0 + rs0;
            lrow[1] = lrow[1] * alpha1 + rs1;
            mrow[0] = mnew0;
            mrow[1] = mnew1;
#pragma unroll
            for (int nj = 0; nj < 8; nj++) {
                oacc[nj][0] *= alpha0; oacc[nj][1] *= alpha0;
                oacc[nj][2] *= alpha1; oacc[nj][3] *= alpha1;
            }
        }

        // O += P @ V
#pragma unroll
        for (int ks = 0; ks < 4; ks++) {
            const int kb = ks * 16;
            unsigned bv[8][2];
#pragma unroll
            for (int njp = 0; njp < 4; njp++) {
                ldm_x4(bv[2 * njp][0], bv[2 * njp][1],
                       bv[2 * njp + 1][0], bv[2 * njp + 1][1],
                       vB + (uint32_t)(((njp * 16 + lr8) * QP_STRIDE + kb + lc8) * 2));
            }
            const unsigned a0 = pf[2 * ks][0];
            const unsigned a1 = pf[2 * ks][1];
            const unsigned a2 = pf[2 * ks + 1][0];
            const unsigned a3 = pf[2 * ks + 1][1];
#pragma unroll
            for (int nj = 0; nj < 8; nj++)
                mma_f16(oacc[nj][0], oacc[nj][1], oacc[nj][2], oacc[nj][3],
                        a0, a1, a2, a3, bv[nj][0], bv[nj][1]);
        }
    }

    // Finalize
    __half* Ob = Og + (size_t)b * SQ * DMODEL + h * HDIM;
    const float inv0 = 1.0f / lrow[0];
    const float inv1 = 1.0f / lrow[1];
    const int row0 = q0 + wrow + g;
#pragma unroll
    for (int nj = 0; nj < 8; nj++) {
        const int col = nj * 8 + tg * 2;
        *(__half2*)(Ob + (size_t)row0 * DMODEL + col) =
            __floats2half2_rn(oacc[nj][0] * inv0, oacc[nj][1] * inv0);
        *(__half2*)(Ob + (size_t)(row0 + 8) * DMODEL + col) =
            __floats2half2_rn(oacc[nj][2] * inv1, oacc[nj][3] * inv1);
    }
}

// ---------------------------------------------------------------------------
// Launch
// ---------------------------------------------------------------------------
extern "C" void kernel_launch(void* const* d_in, const int* in_sizes, int n_in,
                              void* d_out, int out_size)
{
    (void)in_sizes; (void)n_in; (void)out_size;

    const float* x  = (const float*)d_in[0];
    const float* W1 = (const float*)d_in[1];
    const float* b1 = (const float*)d_in[2];
    const float* W2 = (const float*)d_in[3];
    const float* b2 = (const float*)d_in[4];
    const float* Wq = (const float*)d_in[5];
    const float* bq = (const float*)d_in[6];
    const float* Wk = (const float*)d_in[7];
    const float* bk = (const float*)d_in[8];
    const float* Wv = (const float*)d_in[9];
    const float* bv = (const float*)d_in[10];
    const float* Wo = (const float*)d_in[11];
    const float* bo = (const float*)d_in[12];
    float* out = (float*)d_out;

    __half *xh, *h1, *xm, *q, *k, *vt, *o;
    __half *w1h, *w2h, *wqh, *wkh, *wvh, *woh;
    cudaGetSymbolAddress((void**)&xh, g_xh);
    cudaGetSymbolAddress((void**)&h1, g_h1);
    cudaGetSymbolAddress((void**)&xm, g_xm);
    cudaGetSymbolAddress((void**)&q,  g_q);
    cudaGetSymbolAddress((void**)&k,  g_k);
    cudaGetSymbolAddress((void**)&vt, g_vt);
    cudaGetSymbolAddress((void**)&o,  g_o);
    cudaGetSymbolAddress((void**)&w1h, g_w1h);
    cudaGetSymbolAddress((void**)&w2h, g_w2h);
    cudaGetSymbolAddress((void**)&wqh, g_wqh);
    cudaGetSymbolAddress((void**)&wkh, g_wkh);
    cudaGetSymbolAddress((void**)&wvh, g_wvh);
    cudaGetSymbolAddress((void**)&woh, g_woh);

    cudaFuncSetAttribute(gemm_f16<1, 1>, cudaFuncAttributeMaxDynamicSharedMemorySize, GSMEM);
    cudaFuncSetAttribute(gemm_f16<0, 1>, cudaFuncAttributeMaxDynamicSharedMemorySize, GSMEM);
    cudaFuncSetAttribute(gemm_f16<0, 0>, cudaFuncAttributeMaxDynamicSharedMemorySize, GSMEM);
    cudaFuncSetAttribute(gemm_qkv, cudaFuncAttributeMaxDynamicSharedMemorySize, GSMEM);
    const int attn_smem = (QTILE * QP_STRIDE + 4 * KVBUF) * (int)sizeof(__half); // 55296
    cudaFuncSetAttribute(attn_f16, cudaFuncAttributeMaxDynamicSharedMemorySize,
                         attn_smem);

    // Fused prep
    Prep pr;
    pr.src[0] = x;  pr.dst[0] = xh;
    pr.src[1] = W1; pr.dst[1] = w1h;
    pr.src[2] = W2; pr.dst[2] = w2h;
    pr.src[3] = Wq; pr.dst[3] = wqh;
    pr.src[4] = Wk; pr.dst[4] = wkh;
    pr.src[5] = Wv; pr.dst[5] = wvh;
    pr.src[6] = Wo; pr.dst[6] = woh;
    const unsigned cnt[7] = {
        (TOK * DMODEL) / 4, (512 * 1024) / 4, (1024 * 512) / 4,
        (512 * 512) / 4, (512 * 512) / 4, (512 * 512) / 4, (512 * 512) / 4 };
    unsigned acc = 0;
    for (int i = 0; i < 7; i++) { pr.cum[i] = acc; acc += cnt[i]; }
    pr.cum[7] = acc;
    prep_all<<<(acc + 255) / 256, 256>>>(pr);

    QKVp qp;
    qp.w[0] = wqh; qp.w[1] = wkh; qp.w[2] = wvh;
    qp.b[0] = bq;  qp.b[1] = bk;  qp.b[2] = bv;
    qp.q = q; qp.k = k; qp.vt = vt;

    dim3 blk(128);
    gemm_f16<1, 1><<<dim3(1024 / 128, TOK / 64), blk, GSMEM>>>(xh, w1h, b1, h1, TOK, 1024, DMODEL);
    gemm_f16<0, 1><<<dim3(DMODEL / 128, TOK / 64), blk, GSMEM>>>(h1, w2h, b2, xm, TOK, DMODEL, 1024);
    gemm_qkv<<<dim3(1536 / 128, TOK / 64), blk, GSMEM>>>(xm, qp, TOK, DMODEL);
    attn_f16<<<dim3(SQ / QTILE, 4 * NHEADS), dim3(256), attn_smem>>>(q, k, vt, o);
    gemm_f16<0, 0><<<dim3(DMODEL / 128, TOK / 64), blk, GSMEM>>>(o, woh, bo, out, TOK, DMODEL, DMODEL);
}

// round 15
// speedup vs baseline: 1.0069x; 1.0069x over previous
#include <cuda_runtime.h>
#include <cuda_fp16.h>
#include <cstdint>

#define TOK    8192
#define DMODEL 512
#define SQ     2048
#define NHEADS 8
#define HDIM   64
#define WIN    5

// ---------------------------------------------------------------------------
// Device scratch (half). Weights in [K][N] layout.
// ---------------------------------------------------------------------------
__device__ __half g_xh[(size_t)TOK * DMODEL];
__device__ __half g_h1[(size_t)TOK * 1024];
__device__ __half g_xm[(size_t)TOK * DMODEL];
__device__ __half g_q [(size_t)TOK * DMODEL];
__device__ __half g_k [(size_t)TOK * DMODEL];
__device__ __half g_vt[(size_t)4 * NHEADS * HDIM * SQ];  // [b*8+h][d][s]
__device__ __half g_o [(size_t)TOK * DMODEL];
__device__ __half g_w1h[(size_t)512 * 1024];
__device__ __half g_w2h[(size_t)1024 * 512];
__device__ __half g_wqh[(size_t)512 * 512];
__device__ __half g_wkh[(size_t)512 * 512];
__device__ __half g_wvh[(size_t)512 * 512];
__device__ __half g_woh[(size_t)512 * 512];

// ---------------------------------------------------------------------------
// helpers
// ---------------------------------------------------------------------------
__device__ __forceinline__ uint32_t smem_u32(const void* p) {
    uint32_t a;
    asm("{ .reg .u64 t; cvta.to.shared.u64 t, %1; cvt.u32.u64 %0, t; }"
        : "=r"(a) : "l"(p));
    return a;
}

#define CP_ASYNC16(dst_u32, src_ptr) \
    asm volatile("cp.async.cg.shared.global [%0], [%1], 16;" \
                 :: "r"(dst_u32), "l"(src_ptr) : "memory")
#define CP_COMMIT() asm volatile("cp.async.commit_group;" ::: "memory")
#define CP_WAIT(n)  asm volatile("cp.async.wait_group %0;" :: "n"(n) : "memory")

__device__ __forceinline__ void mma_f16(
    float& d0, float& d1, float& d2, float& d3,
    unsigned a0, unsigned a1, unsigned a2, unsigned a3,
    unsigned b0, unsigned b1)
{
    asm volatile(
        "mma.sync.aligned.m16n8k16.row.col.f32.f16.f16.f32 "
        "{%0,%1,%2,%3},{%4,%5,%6,%7},{%8,%9},{%0,%1,%2,%3};\n"
        : "+f"(d0), "+f"(d1), "+f"(d2), "+f"(d3)
        : "r"(a0), "r"(a1), "r"(a2), "r"(a3), "r"(b0), "r"(b1));
}

__device__ __forceinline__ void ldm_x4(
    unsigned& r0, unsigned& r1, unsigned& r2, unsigned& r3, uint32_t addr)
{
    asm volatile("ldmatrix.sync.aligned.m8n8.x4.shared.b16 {%0,%1,%2,%3}, [%4];"
        : "=r"(r0), "=r"(r1), "=r"(r2), "=r"(r3) : "r"(addr));
}

__device__ __forceinline__ void ldm_x4_t(
    unsigned& r0, unsigned& r1, unsigned& r2, unsigned& r3, uint32_t addr)
{
    asm volatile("ldmatrix.sync.aligned.m8n8.x4.trans.shared.b16 {%0,%1,%2,%3}, [%4];"
        : "=r"(r0), "=r"(r1), "=r"(r2), "=r"(r3) : "r"(addr));
}

__device__ __forceinline__ unsigned h2u(__half2 h) {
    return *(unsigned*)&h;
}

// ---------------------------------------------------------------------------
// Fused prep: fp32 -> half for x + 6 weights in ONE launch.
// ---------------------------------------------------------------------------
struct Prep {
    const float* src[7];
    __half* dst[7];
    unsigned cum[8];
};

__global__ __launch_bounds__(256) void prep_all(Prep p)
{
    const unsigned i = blockIdx.x * 256 + threadIdx.x;
    if (i >= p.cum[7]) return;
    int s = 0;
#pragma unroll
    for (int j = 1; j < 7; j++) s += (i >= p.cum[j]) ? 1 : 0;
    const unsigned off = i - p.cum[s];
    float4 v = ((const float4*)p.src[s])[off];
    __half2* d = (__half2*)(p.dst[s] + (size_t)off * 4);
    d[0] = __floats2half2_rn(v.x, v.y);
    d[1] = __floats2half2_rn(v.z, v.w);
}

// ---------------------------------------------------------------------------
// FP16 GEMM, persistent tiles: C[M,N] = act(A[M,K] @ W[K,N] + bias)
// Tile: BM=64, BN=128, BK=64; 128 threads = 4 warps (2x2), warp tile 32x64.
// 2-stage cp.async, single barrier per k-iter. Grid-stride over tiles.
// ---------------------------------------------------------------------------
#define AP2 72     // A row stride in halves (64+8)
#define BPH 136    // B row stride in halves (128+8)
#define A_ST (64 * AP2 * 2)          // 9216 B per A stage
#define B_ST (64 * BPH * 2)          // 17408 B per B stage
#define GSMEM (2 * (A_ST + B_ST))    // 53248
#define NPERS 592                    // 148 SMs x 4 blocks

template<int RELU, int OMODE>
__global__ void __launch_bounds__(128, 4) gemm_f16(
    const __half* __restrict__ A, const __half* __restrict__ W,
    const float* __restrict__ bias, void* __restrict__ Cv,
    int M, int N, int K)
{
    extern __shared__ __half smg[];
    const uint32_t aBase = smem_u32(smg);
    const uint32_t bBase = aBase + 2 * A_ST;

    const int tid  = threadIdx.x;
    const int warp = tid >> 5;
    const int lane = tid & 31;
    const int g    = lane >> 2;
    const int tg   = lane & 3;
    const int wm   = warp >> 1;
    const int wn   = warp & 1;
    const int lrow = lane & 15;
    const int lcol = (lane >> 4) << 3;

    const int nx = N >> 7;
    const int ntiles = (M >> 6) * nx;
    const int nt = K >> 6;

    for (int tile = blockIdx.x; tile < ntiles; tile += gridDim.x) {
        const int m0 = (tile / nx) << 6;
        const int n0 = (tile % nx) << 7;

        float acc[2][8][4];
#pragma unroll
        for (int mi = 0; mi < 2; mi++)
#pragma unroll
            for (int nj = 0; nj < 8; nj++)
#pragma unroll
                for (int r = 0; r < 4; r++) acc[mi][nj][r] = 0.f;

        auto issue = [&](int kt, int slot) {
            const int k0 = kt << 6;
            const uint32_t aOff = aBase + slot * A_ST;
            const uint32_t bOff = bBase + slot * B_ST;
#pragma unroll
            for (int t = 0; t < 4; t++) {
                const int ia = tid + t * 128;
                const int ra = ia >> 3, ca = ia & 7;
                CP_ASYNC16(aOff + (uint32_t)(ra * AP2 * 2 + ca * 16),
                           A + (size_t)(m0 + ra) * K + k0 + ca * 8);
            }
#pragma unroll
            for (int t = 0; t < 8; t++) {
                const int ib = tid + t * 128;
                const int rb = ib >> 4, cb = ib & 15;
                CP_ASYNC16(bOff + (uint32_t)(rb * BPH * 2 + cb * 16),
                           W + (size_t)(k0 + rb) * N + n0 + cb * 8);
            }
            CP_COMMIT();
        };

        __syncthreads();    // previous tile's compute done before smem reuse
        issue(0, 0);

        for (int kt = 0; kt < nt; kt++) {
            const int slot = kt & 1;
            CP_WAIT(0);
            __syncthreads();
            if (kt + 1 < nt) issue(kt + 1, slot ^ 1);

            const uint32_t aB = aBase + slot * A_ST;
            const uint32_t bB = bBase + slot * B_ST;

#pragma unroll
            for (int ks = 0; ks < 4; ks++) {
                const int kb = ks * 16;
                unsigned a[2][4];
#pragma unroll
                for (int mi = 0; mi < 2; mi++) {
                    const int row0 = wm * 32 + mi * 16;
                    ldm_x4(a[mi][0], a[mi][1], a[mi][2], a[mi][3],
                           aB + (uint32_t)(((row0 + lrow) * AP2 + kb + lcol) * 2));
                }
                unsigned b[8][2];
#pragma unroll
                for (int njp = 0; njp < 4; njp++) {
                    const int col0 = wn * 64 + njp * 16;
                    ldm_x4_t(b[2 * njp][0], b[2 * njp][1],
                             b[2 * njp + 1][0], b[2 * njp + 1][1],
                             bB + (uint32_t)(((kb + lrow) * BPH + col0 + lcol) * 2));
                }
#pragma unroll
                for (int mi = 0; mi < 2; mi++)
#pragma unroll
                    for (int nj = 0; nj < 8; nj++)
                        mma_f16(acc[mi][nj][0], acc[mi][nj][1],
                                acc[mi][nj][2], acc[mi][nj][3],
                                a[mi][0], a[mi][1], a[mi][2], a[mi][3],
                                b[nj][0], b[nj][1]);
            }
        }

        // Epilogue
#pragma unroll
        for (int mi = 0; mi < 2; mi++) {
            const int row = m0 + wm * 32 + mi * 16 + g;
#pragma unroll
            for (int nj = 0; nj < 8; nj++) {
                const int col = n0 + wn * 64 + nj * 8 + tg * 2;
                float2 bv = *(const float2*)(bias + col);
                float c0x = acc[mi][nj][0] + bv.x;
                float c0y = acc[mi][nj][1] + bv.y;
                float c1x = acc[mi][nj][2] + bv.x;
                float c1y = acc[mi][nj][3] + bv.y;
                if (RELU) {
                    c0x = fmaxf(c0x, 0.f); c0y = fmaxf(c0y, 0.f);
                    c1x = fmaxf(c1x, 0.f); c1y = fmaxf(c1y, 0.f);
                }
                if (OMODE == 0) {
                    float* C = (float*)Cv;
                    float2 u; u.x = c0x; u.y = c0y;
                    float2 w; w.x = c1x; w.y = c1y;
                    *(float2*)(C + (size_t)row * N + col)       = u;
                    *(float2*)(C + (size_t)(row + 8) * N + col) = w;
                } else {
                    __half* C = (__half*)Cv;
                    *(__half2*)(C + (size_t)row * N + col)       = __floats2half2_rn(c0x, c0y);
                    *(__half2*)(C + (size_t)(row + 8) * N + col) = __floats2half2_rn(c1x, c1y);
                }
            }
        }
    }
}

// ---------------------------------------------------------------------------
// Fused QKV GEMM, persistent tiles: N=1536 regions q/k/vt.
// ---------------------------------------------------------------------------
struct QKVp {
    const __half* w[3];
    const float*  b[3];
    __half* q; __half* k; __half* vt;
};

__global__ void __launch_bounds__(128, 4) gemm_qkv(
    const __half* __restrict__ A, QKVp p, int M, int K)
{
    extern __shared__ __half smg[];
    const uint32_t aBase = smem_u32(smg);
    const uint32_t bBase = aBase + 2 * A_ST;

    const int tid  = threadIdx.x;
    const int warp = tid >> 5;
    const int lane = tid & 31;
    const int g    = lane >> 2;
    const int tg   = lane & 3;
    const int wm   = warp >> 1;
    const int wn   = warp & 1;
    const int lrow = lane & 15;
    const int lcol = (lane >> 4) << 3;

    const int nx = 12;                    // 1536 / 128
    const int ntiles = (M >> 6) * nx;
    const int nt = K >> 6;

    for (int tile = blockIdx.x; tile < ntiles; tile += gridDim.x) {
        const int m0  = (tile / nx) << 6;
        const int n0g = (tile % nx) << 7;
        const int reg = n0g >> 9;
        const int n0  = n0g & 511;
        const __half* W = p.w[reg];
        const float* bias = p.b[reg];

        float acc[2][8][4];
#pragma unroll
        for (int mi = 0; mi < 2; mi++)
#pragma unroll
            for (int nj = 0; nj < 8; nj++)
#pragma unroll
                for (int r = 0; r < 4; r++) acc[mi][nj][r] = 0.f;

        auto issue = [&](int kt, int slot) {
            const int k0 = kt << 6;
            const uint32_t aOff = aBase + slot * A_ST;
            const uint32_t bOff = bBase + slot * B_ST;
#pragma unroll
            for (int t = 0; t < 4; t++) {
                const int ia = tid + t * 128;
                const int ra = ia >> 3, ca = ia & 7;
                CP_ASYNC16(aOff + (uint32_t)(ra * AP2 * 2 + ca * 16),
                           A + (size_t)(m0 + ra) * K + k0 + ca * 8);
            }
#pragma unroll
            for (int t = 0; t < 8; t++) {
                const int ib = tid + t * 128;
                const int rb = ib >> 4, cb = ib & 15;
                CP_ASYNC16(bOff + (uint32_t)(rb * BPH * 2 + cb * 16),
                           W + (size_t)(k0 + rb) * 512 + n0 + cb * 8);
            }
            CP_COMMIT();
        };

        __syncthreads();
        issue(0, 0);

        for (int kt = 0; kt < nt; kt++) {
            const int slot = kt & 1;
            CP_WAIT(0);
            __syncthreads();
            if (kt + 1 < nt) issue(kt + 1, slot ^ 1);

            const uint32_t aB = aBase + slot * A_ST;
            const uint32_t bB = bBase + slot * B_ST;

#pragma unroll
            for (int ks = 0; ks < 4; ks++) {
                const int kb = ks * 16;
                unsigned a[2][4];
#pragma unroll
                for (int mi = 0; mi < 2; mi++) {
                    const int row0 = wm * 32 + mi * 16;
                    ldm_x4(a[mi][0], a[mi][1], a[mi][2], a[mi][3],
                           aB + (uint32_t)(((row0 + lrow) * AP2 + kb + lcol) * 2));
                }
                unsigned b[8][2];
#pragma unroll
                for (int njp = 0; njp < 4; njp++) {
                    const int col0 = wn * 64 + njp * 16;
                    ldm_x4_t(b[2 * njp][0], b[2 * njp][1],
                             b[2 * njp + 1][0], b[2 * njp + 1][1],
                             bB + (uint32_t)(((kb + lrow) * BPH + col0 + lcol) * 2));
                }
#pragma unroll
                for (int mi = 0; mi < 2; mi++)
#pragma unroll
                    for (int nj = 0; nj < 8; nj++)
                        mma_f16(acc[mi][nj][0], acc[mi][nj][1],
                                acc[mi][nj][2], acc[mi][nj][3],
                                a[mi][0], a[mi][1], a[mi][2], a[mi][3],
                                b[nj][0], b[nj][1]);
            }
        }

#pragma unroll
        for (int mi = 0; mi < 2; mi++) {
            const int row = m0 + wm * 32 + mi * 16 + g;
#pragma unroll
            for (int nj = 0; nj < 8; nj++) {
                const int coln = n0 + wn * 64 + nj * 8 + tg * 2;
                float2 bv = *(const float2*)(bias + coln);
                const float c0x = acc[mi][nj][0] + bv.x;
                const float c0y = acc[mi][nj][1] + bv.y;
                const float c1x = acc[mi][nj][2] + bv.x;
                const float c1y = acc[mi][nj][3] + bv.y;
                if (reg == 2) {
                    __half* C = p.vt;
                    const int b = row >> 11, s = row & 2047;
                    const int h = coln >> 6, dd = coln & 63;
                    const size_t base = (((size_t)(b * 8 + h) * 64 + dd) << 11);
                    C[base + s]            = __float2half_rn(c0x);
                    C[base + 2048 + s]     = __float2half_rn(c0y);
                    C[base + s + 8]        = __float2half_rn(c1x);
                    C[base + 2048 + s + 8] = __float2half_rn(c1y);
                } else {
                    __half* C = (reg == 0) ? p.q : p.k;
                    *(__half2*)(C + (size_t)row * DMODEL + coln)       = __floats2half2_rn(c0x, c0y);
                    *(__half2*)(C + (size_t)(row + 8) * DMODEL + coln) = __floats2half2_rn(c1x, c1y);
                }
            }
        }
    }
}

// ---------------------------------------------------------------------------
// FP16 flash attention (round-12 config): QTILE=256, register-resident P,
// cp.async pipeline, single barrier per kt, exp2 softmax.
// ---------------------------------------------------------------------------
#define QP_STRIDE 72
#define QTILE 256
#define KVBUF (64 * QP_STRIDE)

__global__ __launch_bounds__(256) void attn_f16(
    const __half* __restrict__ Qg, const __half* __restrict__ Kg,
    const __half* __restrict__ Vt, __half* __restrict__ Og)
{
    extern __shared__ __half smh[];
    __half (*QP)[QP_STRIDE] = (__half(*)[QP_STRIDE])smh;
    __half* KsBase = smh + QTILE * QP_STRIDE;
    __half* VsBase = KsBase + 2 * KVBUF;

    const int tid  = threadIdx.x;
    const int warp = tid >> 5;
    const int lane = tid & 31;
    const int g    = lane >> 2;
    const int tg   = lane & 3;
    const int bh   = blockIdx.y;
    const int b    = bh >> 3;
    const int h    = bh & 7;
    const int q0   = blockIdx.x * QTILE;
    const int wrow = warp * 32;

    const uint32_t qpB = smem_u32(&QP[0][0]);
    const uint32_t ksB = smem_u32(KsBase);
    const uint32_t vsB = smem_u32(VsBase);
    const int lr16 = lane & 15;
    const int lc16 = (lane >> 4) << 3;
    const int lr8  = (lane & 7) + ((lane >> 4) << 3);
    const int lc8  = ((lane >> 3) & 1) << 3;

    const __half* Qb  = Qg + (size_t)b * SQ * DMODEL + h * HDIM;
    const __half* Kb  = Kg + (size_t)b * SQ * DMODEL + h * HDIM;
    const __half* Vtb = Vt + (size_t)bh * HDIM * SQ;

    const __half2 sc = __float2half2_rn(0.125f * 1.4426950408889634f);
#pragma unroll
    for (int t = 0; t < 8; t++) {
        const int idx = tid + t * 256;
        const int r = idx >> 3, c = (idx & 7) * 8;
        uint4 v = *(const uint4*)(Qb + (size_t)(q0 + r) * DMODEL + c);
        __half2* pv = (__half2*)&v;
#pragma unroll
        for (int j = 0; j < 4; j++) pv[j] = __hmul2(pv[j], sc);
        *(uint4*)&QP[r][c] = v;
    }

#pragma unroll
    for (int t = 0; t < 2; t++) {
        const int idx = tid + t * 256;
        const int r = idx >> 3, c = (idx & 7) * 8;
        CP_ASYNC16(ksB + (uint32_t)((r * QP_STRIDE + c) * 2),
                   Kb + (size_t)r * DMODEL + c);
        CP_ASYNC16(vsB + (uint32_t)((r * QP_STRIDE + c) * 2),
                   Vtb + (size_t)r * SQ + c);
    }
    CP_COMMIT();
    __syncthreads();

    unsigned qf[4][2][4];
#pragma unroll
    for (int ks = 0; ks < 4; ks++) {
        const int kb = ks * 16;
#pragma unroll
        for (int mi = 0; mi < 2; mi++) {
            const int row0 = wrow + mi * 16;
            ldm_x4(qf[ks][mi][0], qf[ks][mi][1], qf[ks][mi][2], qf[ks][mi][3],
                   qpB + (uint32_t)(((row0 + lr16) * QP_STRIDE + kb + lc16) * 2));
        }
    }

    float oacc[2][8][4];
#pragma unroll
    for (int mi = 0; mi < 2; mi++)
#pragma unroll
        for (int nj = 0; nj < 8; nj++)
#pragma unroll
            for (int r = 0; r < 4; r++) oacc[mi][nj][r] = 0.f;
    float mrow[2][2], lrow[2][2];
#pragma unroll
    for (int mi = 0; mi < 2; mi++) {
        mrow[mi][0] = mrow[mi][1] = -1e30f;
        lrow[mi][0] = lrow[mi][1] = 0.f;
    }

    const int NT = SQ / 64;
    for (int kt = 0; kt < NT; kt++) {
        const int k0 = kt * 64;
        const int buf = kt & 1;

        CP_WAIT(0);
        __syncthreads();

        if (kt + 1 < NT) {
            const int kn = (kt + 1) * 64;
            const uint32_t kOff = ksB + (buf ^ 1) * KVBUF * 2;
            const uint32_t vOff = vsB + (buf ^ 1) * KVBUF * 2;
#pragma unroll
            for (int t = 0; t < 2; t++) {
                const int idx = tid + t * 256;
                const int r = idx >> 3, c = (idx & 7) * 8;
                CP_ASYNC16(kOff + (uint32_t)((r * QP_STRIDE + c) * 2),
                           Kb + (size_t)(kn + r) * DMODEL + c);
                CP_ASYNC16(vOff + (uint32_t)((r * QP_STRIDE + c) * 2),
                           Vtb + (size_t)r * SQ + kn + c);
            }
            CP_COMMIT();
        }

        const uint32_t kB = ksB + buf * KVBUF * 2;
        const uint32_t vB = vsB + buf * KVBUF * 2;

        float sfrag[2][8][4];
#pragma unroll
        for (int mi = 0; mi < 2; mi++)
#pragma unroll
            for (int nj = 0; nj < 8; nj++)
#pragma unroll
                for (int r = 0; r < 4; r++) sfrag[mi][nj][r] = 0.f;

#pragma unroll
        for (int ks = 0; ks < 4; ks++) {
            const int kb = ks * 16;
            unsigned bq[8][2];
#pragma unroll
            for (int njp = 0; njp < 4; njp++) {
                ldm_x4(bq[2 * njp][0], bq[2 * njp][1],
                       bq[2 * njp + 1][0], bq[2 * njp + 1][1],
                       kB + (uint32_t)(((njp * 16 + lr8) * QP_STRIDE + kb + lc8) * 2));
            }
#pragma unroll
            for (int mi = 0; mi < 2; mi++)
#pragma unroll
                for (int nj = 0; nj < 8; nj++)
                    mma_f16(sfrag[mi][nj][0], sfrag[mi][nj][1],
                            sfrag[mi][nj][2], sfrag[mi][nj][3],
                            qf[ks][mi][0], qf[ks][mi][1],
                            qf[ks][mi][2], qf[ks][mi][3],
                            bq[nj][0], bq[nj][1]);
        }

        const bool need_mask = (k0 <= q0 + QTILE - 1 + WIN) && (k0 + 63 >= q0 - WIN);
        if (need_mask) {
#pragma unroll
            for (int mi = 0; mi < 2; mi++) {
                const int qr0 = q0 + wrow + mi * 16 + g;
                const int qr1 = qr0 + 8;
#pragma unroll
                for (int nj = 0; nj < 8; nj++) {
                    const int kc0 = k0 + nj * 8 + tg * 2;
                    if ((unsigned)(qr0 - kc0     + WIN) <= 2 * WIN) sfrag[mi][nj][0] = -1e9f;
                    if ((unsigned)(qr0 - kc0 - 1 + WIN) <= 2 * WIN) sfrag[mi][nj][1] = -1e9f;
                    if ((unsigned)(qr1 - kc0     + WIN) <= 2 * WIN) sfrag[mi][nj][2] = -1e9f;
                    if ((unsigned)(qr1 - kc0 - 1 + WIN) <= 2 * WIN) sfrag[mi][nj][3] = -1e9f;
                }
            }
        }

        unsigned pf[2][8][2];
#pragma unroll
        for (int mi = 0; mi < 2; mi++) {
            float tmax0 = -1e30f, tmax1 = -1e30f;
#pragma unroll
            for (int nj = 0; nj < 8; nj++) {
                tmax0 = fmaxf(tmax0, fmaxf(sfrag[mi][nj][0], sfrag[mi][nj][1]));
                tmax1 = fmaxf(tmax1, fmaxf(sfrag[mi][nj][2], sfrag[mi][nj][3]));
            }
#pragma unroll
            for (int off = 1; off <= 2; off <<= 1) {
                tmax0 = fmaxf(tmax0, __shfl_xor_sync(0xffffffffu, tmax0, off));
                tmax1 = fmaxf(tmax1, __shfl_xor_sync(0xffffffffu, tmax1, off));
            }
            const float mnew0 = fmaxf(mrow[mi][0], tmax0);
            const float mnew1 = fmaxf(mrow[mi][1], tmax1);
            const float alpha0 = exp2f(mrow[mi][0] - mnew0);
            const float alpha1 = exp2f(mrow[mi][1] - mnew1);

            float rs0 = 0.f, rs1 = 0.f;
#pragma unroll
            for (int nj = 0; nj < 8; nj++) {
                const float p0 = exp2f(sfrag[mi][nj][0] - mnew0);
                const float p1 = exp2f(sfrag[mi][nj][1] - mnew0);
                const float p2 = exp2f(sfrag[mi][nj][2] - mnew1);
                const float p3 = exp2f(sfrag[mi][nj][3] - mnew1);
                rs0 += p0 + p1;
                rs1 += p2 + p3;
                pf[mi][nj][0] = h2u(__floats2half2_rn(p0, p1));
                pf[mi][nj][1] = h2u(__floats2half2_rn(p2, p3));
            }
#pragma unroll
            for (int off = 1; off <= 2; off <<= 1) {
                rs0 += __shfl_xor_sync(0xffffffffu, rs0, off);
                rs1 += __shfl_xor_sync(0xffffffffu, rs1, off);
            }
            lrow[mi][0] = lrow[mi][0] * alpha0 + rs0;
            lrow[mi][1] = lrow[mi][1] * alpha1 + rs1;
            mrow[mi][0] = mnew0;
            mrow[mi][1] = mnew1;
#pragma unroll
            for (int nj = 0; nj < 8; nj++) {
                oacc[mi][nj][0] *= alpha0; oacc[mi][nj][1] *= alpha0;
                oacc[mi][nj][2] *= alpha1; oacc[mi][nj][3] *= alpha1;
            }
        }

#pragma unroll
        for (int ks = 0; ks < 4; ks++) {
            const int kb = ks * 16;
            unsigned bv[8][2];
#pragma unroll
            for (int njp = 0; njp < 4; njp++) {
                ldm_x4(bv[2 * njp][0], bv[2 * njp][1],
                       bv[2 * njp + 1][0], bv[2 * njp + 1][1],
                       vB + (uint32_t)(((njp * 16 + lr8) * QP_STRIDE + kb + lc8) * 2));
            }
#pragma unroll
            for (int mi = 0; mi < 2; mi++) {
                const unsigned a0 = pf[mi][2 * ks][0];
                const unsigned a1 = pf[mi][2 * ks][1];
                const unsigned a2 = pf[mi][2 * ks + 1][0];
                const unsigned a3 = pf[mi][2 * ks + 1][1];
#pragma unroll
                for (int nj = 0; nj < 8; nj++)
                    mma_f16(oacc[mi][nj][0], oacc[mi][nj][1],
                            oacc[mi][nj][2], oacc[mi][nj][3],
                            a0, a1, a2, a3, bv[nj][0], bv[nj][1]);
            }
        }
    }

    __half* Ob = Og + (size_t)b * SQ * DMODEL + h * HDIM;
#pragma unroll
    for (int mi = 0; mi < 2; mi++) {
        const float inv0 = 1.0f / lrow[mi][0];
        const float inv1 = 1.0f / lrow[mi][1];
        const int row0 = q0 + wrow + mi * 16 + g;
#pragma unroll
        for (int nj = 0; nj < 8; nj++) {
            const int col = nj * 8 + tg * 2;
            *(__half2*)(Ob + (size_t)row0 * DMODEL + col) =
                __floats2half2_rn(oacc[mi][nj][0] * inv0, oacc[mi][nj][1] * inv0);
            *(__half2*)(Ob + (size_t)(row0 + 8) * DMODEL + col) =
                __floats2half2_rn(oacc[mi][nj][2] * inv1, oacc[mi][nj][3] * inv1);
        }
    }
}

// ---------------------------------------------------------------------------
// Launch
// ---------------------------------------------------------------------------
extern "C" void kernel_launch(void* const* d_in, const int* in_sizes, int n_in,
                              void* d_out, int out_size)
{
    (void)in_sizes; (void)n_in; (void)out_size;

    const float* x  = (const float*)d_in[0];
    const float* W1 = (const float*)d_in[1];
    const float* b1 = (const float*)d_in[2];
    const float* W2 = (const float*)d_in[3];
    const float* b2 = (const float*)d_in[4];
    const float* Wq = (const float*)d_in[5];
    const float* bq = (const float*)d_in[6];
    const float* Wk = (const float*)d_in[7];
    const float* bk = (const float*)d_in[8];
    const float* Wv = (const float*)d_in[9];
    const float* bv = (const float*)d_in[10];
    const float* Wo = (const float*)d_in[11];
    const float* bo = (const float*)d_in[12];
    float* out = (float*)d_out;

    __half *xh, *h1, *xm, *q, *k, *vt, *o;
    __half *w1h, *w2h, *wqh, *wkh, *wvh, *woh;
    cudaGetSymbolAddress((void**)&xh, g_xh);
    cudaGetSymbolAddress((void**)&h1, g_h1);
    cudaGetSymbolAddress((void**)&xm, g_xm);
    cudaGetSymbolAddress((void**)&q,  g_q);
    cudaGetSymbolAddress((void**)&k,  g_k);
    cudaGetSymbolAddress((void**)&vt, g_vt);
    cudaGetSymbolAddress((void**)&o,  g_o);
    cudaGetSymbolAddress((void**)&w1h, g_w1h);
    cudaGetSymbolAddress((void**)&w2h, g_w2h);
    cudaGetSymbolAddress((void**)&wqh, g_wqh);
    cudaGetSymbolAddress((void**)&wkh, g_wkh);
    cudaGetSymbolAddress((void**)&wvh, g_wvh);
    cudaGetSymbolAddress((void**)&woh, g_woh);

    cudaFuncSetAttribute(gemm_f16<1, 1>, cudaFuncAttributeMaxDynamicSharedMemorySize, GSMEM);
    cudaFuncSetAttribute(gemm_f16<0, 1>, cudaFuncAttributeMaxDynamicSharedMemorySize, GSMEM);
    cudaFuncSetAttribute(gemm_f16<0, 0>, cudaFuncAttributeMaxDynamicSharedMemorySize, GSMEM);
    cudaFuncSetAttribute(gemm_qkv, cudaFuncAttributeMaxDynamicSharedMemorySize, GSMEM);
    const int attn_smem = (QTILE * QP_STRIDE + 4 * KVBUF) * (int)sizeof(__half); // 73728
    cudaFuncSetAttribute(attn_f16, cudaFuncAttributeMaxDynamicSharedMemorySize,
                         attn_smem);

    // Fused prep
    Prep pr;
    pr.src[0] = x;  pr.dst[0] = xh;
    pr.src[1] = W1; pr.dst[1] = w1h;
    pr.src[2] = W2; pr.dst[2] = w2h;
    pr.src[3] = Wq; pr.dst[3] = wqh;
    pr.src[4] = Wk; pr.dst[4] = wkh;
    pr.src[5] = Wv; pr.dst[5] = wvh;
    pr.src[6] = Wo; pr.dst[6] = woh;
    const unsigned cnt[7] = {
        (TOK * DMODEL) / 4, (512 * 1024) / 4, (1024 * 512) / 4,
        (512 * 512) / 4, (512 * 512) / 4, (512 * 512) / 4, (512 * 512) / 4 };
    unsigned acc = 0;
    for (int i = 0; i < 7; i++) { pr.cum[i] = acc; acc += cnt[i]; }
    pr.cum[7] = acc;
    prep_all<<<(acc + 255) / 256, 256>>>(pr);

    QKVp qp;
    qp.w[0] = wqh; qp.w[1] = wkh; qp.w[2] = wvh;
    qp.b[0] = bq;  qp.b[1] = bk;  qp.b[2] = bv;
    qp.q = q; qp.k = k; qp.vt = vt;

    dim3 blk(128);
    const int t_mlp1 = (TOK / 64) * (1024 / 128);   // 1024
    const int t_n512 = (TOK / 64) * (512 / 128);    // 512
    const int t_qkv  = (TOK / 64) * 12;             // 1536
    const int g_mlp1 = t_mlp1 < NPERS ? t_mlp1 : NPERS;
    const int g_n512 = t_n512 < NPERS ? t_n512 : NPERS;
    const int g_qkv  = t_qkv  < NPERS ? t_qkv  : NPERS;

    gemm_f16<1, 1><<<g_mlp1, blk, GSMEM>>>(xh, w1h, b1, h1, TOK, 1024, DMODEL);
    gemm_f16<0, 1><<<g_n512, blk, GSMEM>>>(h1, w2h, b2, xm, TOK, DMODEL, 1024);
    gemm_qkv<<<g_qkv, blk, GSMEM>>>(xm, qp, TOK, DMODEL);
    attn_f16<<<dim3(SQ / QTILE, 4 * NHEADS), dim3(256), attn_smem>>>(q, k, vt, o);
    gemm_f16<0, 0><<<g_n512, blk, GSMEM>>>(o, woh, bo, out, TOK, DMODEL, DMODEL);
}

// round 16
// speedup vs baseline: 1.0252x; 1.0182x over previous
#include <cuda_runtime.h>
#include <cuda_fp16.h>
#include <cstdint>

#define TOK    8192
#define DMODEL 512
#define SQ     2048
#define NHEADS 8
#define HDIM   64
#define WIN    5

// ---------------------------------------------------------------------------
// Device scratch (half). Weights in [K][N] layout.
// ---------------------------------------------------------------------------
__device__ __half g_xh[(size_t)TOK * DMODEL];
__device__ __half g_h1[(size_t)TOK * 1024];
__device__ __half g_xm[(size_t)TOK * DMODEL];
__device__ __half g_q [(size_t)TOK * DMODEL];
__device__ __half g_k [(size_t)TOK * DMODEL];
__device__ __half g_vt[(size_t)4 * NHEADS * HDIM * SQ];  // [b*8+h][d][s]
__device__ __half g_o [(size_t)TOK * DMODEL];
__device__ __half g_w1h[(size_t)512 * 1024];
__device__ __half g_w2h[(size_t)1024 * 512];
__device__ __half g_wqh[(size_t)512 * 512];
__device__ __half g_wkh[(size_t)512 * 512];
__device__ __half g_wvh[(size_t)512 * 512];
__device__ __half g_woh[(size_t)512 * 512];

// ---------------------------------------------------------------------------
// helpers
// ---------------------------------------------------------------------------
__device__ __forceinline__ uint32_t smem_u32(const void* p) {
    uint32_t a;
    asm("{ .reg .u64 t; cvta.to.shared.u64 t, %1; cvt.u32.u64 %0, t; }"
        : "=r"(a) : "l"(p));
    return a;
}

#define CP_ASYNC16(dst_u32, src_ptr) \
    asm volatile("cp.async.cg.shared.global [%0], [%1], 16;" \
                 :: "r"(dst_u32), "l"(src_ptr) : "memory")
#define CP_ASYNC16_CA(dst_u32, src_ptr) \
    asm volatile("cp.async.ca.shared.global [%0], [%1], 16;" \
                 :: "r"(dst_u32), "l"(src_ptr) : "memory")
#define CP_COMMIT() asm volatile("cp.async.commit_group;" ::: "memory")
#define CP_WAIT(n)  asm volatile("cp.async.wait_group %0;" :: "n"(n) : "memory")

__device__ __forceinline__ void mma_f16(
    float& d0, float& d1, float& d2, float& d3,
    unsigned a0, unsigned a1, unsigned a2, unsigned a3,
    unsigned b0, unsigned b1)
{
    asm volatile(
        "mma.sync.aligned.m16n8k16.row.col.f32.f16.f16.f32 "
        "{%0,%1,%2,%3},{%4,%5,%6,%7},{%8,%9},{%0,%1,%2,%3};\n"
        : "+f"(d0), "+f"(d1), "+f"(d2), "+f"(d3)
        : "r"(a0), "r"(a1), "r"(a2), "r"(a3), "r"(b0), "r"(b1));
}

__device__ __forceinline__ void ldm_x4(
    unsigned& r0, unsigned& r1, unsigned& r2, unsigned& r3, uint32_t addr)
{
    asm volatile("ldmatrix.sync.aligned.m8n8.x4.shared.b16 {%0,%1,%2,%3}, [%4];"
        : "=r"(r0), "=r"(r1), "=r"(r2), "=r"(r3) : "r"(addr));
}

__device__ __forceinline__ void ldm_x4_t(
    unsigned& r0, unsigned& r1, unsigned& r2, unsigned& r3, uint32_t addr)
{
    asm volatile("ldmatrix.sync.aligned.m8n8.x4.trans.shared.b16 {%0,%1,%2,%3}, [%4];"
        : "=r"(r0), "=r"(r1), "=r"(r2), "=r"(r3) : "r"(addr));
}

__device__ __forceinline__ unsigned h2u(__half2 h) {
    return *(unsigned*)&h;
}

// ---------------------------------------------------------------------------
// Fused prep: fp32 -> half for x + 6 weights in ONE launch.
// ---------------------------------------------------------------------------
struct Prep {
    const float* src[7];
    __half* dst[7];
    unsigned cum[8];
};

__global__ __launch_bounds__(256) void prep_all(Prep p)
{
    const unsigned i = blockIdx.x * 256 + threadIdx.x;
    if (i >= p.cum[7]) return;
    int s = 0;
#pragma unroll
    for (int j = 1; j < 7; j++) s += (i >= p.cum[j]) ? 1 : 0;
    const unsigned off = i - p.cum[s];
    float4 v = ((const float4*)p.src[s])[off];
    __half2* d = (__half2*)(p.dst[s] + (size_t)off * 4);
    d[0] = __floats2half2_rn(v.x, v.y);
    d[1] = __floats2half2_rn(v.z, v.w);
}

// ---------------------------------------------------------------------------
// FP16 GEMM (round-12 config): BM=64, BN=128, BK=64; 128 threads, 4 warps,
// warp tile 32x64, 2-stage cp.async, single barrier per k-iter.
// A tiles via .ca (shared across co-resident blocks with same m0); B via .cg.
// ---------------------------------------------------------------------------
#define AP2 72     // A row stride in halves (64+8)
#define BPH 136    // B row stride in halves (128+8)
#define A_ST (64 * AP2 * 2)          // 9216 B per A stage
#define B_ST (64 * BPH * 2)          // 17408 B per B stage
#define GSMEM (2 * (A_ST + B_ST))    // 53248

template<int RELU, int OMODE>
__global__ void __launch_bounds__(128, 4) gemm_f16(
    const __half* __restrict__ A, const __half* __restrict__ W,
    const float* __restrict__ bias, void* __restrict__ Cv,
    int M, int N, int K)
{
    extern __shared__ __half smg[];
    const uint32_t aBase = smem_u32(smg);
    const uint32_t bBase = aBase + 2 * A_ST;

    const int tid  = threadIdx.x;
    const int warp = tid >> 5;
    const int lane = tid & 31;
    const int g    = lane >> 2;
    const int tg   = lane & 3;
    const int wm   = warp >> 1;
    const int wn   = warp & 1;
    const int m0   = blockIdx.y * 64;
    const int n0   = blockIdx.x * 128;

    float acc[2][8][4];
#pragma unroll
    for (int mi = 0; mi < 2; mi++)
#pragma unroll
        for (int nj = 0; nj < 8; nj++)
#pragma unroll
            for (int r = 0; r < 4; r++) acc[mi][nj][r] = 0.f;

    const int nt = K >> 6;

    auto issue = [&](int kt, int slot) {
        const int k0 = kt << 6;
        const uint32_t aOff = aBase + slot * A_ST;
        const uint32_t bOff = bBase + slot * B_ST;
#pragma unroll
        for (int t = 0; t < 4; t++) {
            const int ia = tid + t * 128;
            const int ra = ia >> 3, ca = ia & 7;
            CP_ASYNC16_CA(aOff + (uint32_t)(ra * AP2 * 2 + ca * 16),
                          A + (size_t)(m0 + ra) * K + k0 + ca * 8);
        }
#pragma unroll
        for (int t = 0; t < 8; t++) {
            const int ib = tid + t * 128;
            const int rb = ib >> 4, cb = ib & 15;
            CP_ASYNC16(bOff + (uint32_t)(rb * BPH * 2 + cb * 16),
                       W + (size_t)(k0 + rb) * N + n0 + cb * 8);
        }
        CP_COMMIT();
    };

    issue(0, 0);

    for (int kt = 0; kt < nt; kt++) {
        const int slot = kt & 1;
        CP_WAIT(0);
        __syncthreads();
        if (kt + 1 < nt) issue(kt + 1, slot ^ 1);

        const uint32_t aB = aBase + slot * A_ST;
        const uint32_t bB = bBase + slot * B_ST;
        const int lrow = lane & 15;
        const int lcol = (lane >> 4) << 3;

#pragma unroll
        for (int ks = 0; ks < 4; ks++) {
            const int kb = ks * 16;
            unsigned a[2][4];
#pragma unroll
            for (int mi = 0; mi < 2; mi++) {
                const int row0 = wm * 32 + mi * 16;
                ldm_x4(a[mi][0], a[mi][1], a[mi][2], a[mi][3],
                       aB + (uint32_t)(((row0 + lrow) * AP2 + kb + lcol) * 2));
            }
            unsigned b[8][2];
#pragma unroll
            for (int njp = 0; njp < 4; njp++) {
                const int col0 = wn * 64 + njp * 16;
                ldm_x4_t(b[2 * njp][0], b[2 * njp][1],
                         b[2 * njp + 1][0], b[2 * njp + 1][1],
                         bB + (uint32_t)(((kb + lrow) * BPH + col0 + lcol) * 2));
            }
#pragma unroll
            for (int mi = 0; mi < 2; mi++)
#pragma unroll
                for (int nj = 0; nj < 8; nj++)
                    mma_f16(acc[mi][nj][0], acc[mi][nj][1],
                            acc[mi][nj][2], acc[mi][nj][3],
                            a[mi][0], a[mi][1], a[mi][2], a[mi][3],
                            b[nj][0], b[nj][1]);
        }
    }

    // Epilogue
#pragma unroll
    for (int mi = 0; mi < 2; mi++) {
        const int row = m0 + wm * 32 + mi * 16 + g;
#pragma unroll
        for (int nj = 0; nj < 8; nj++) {
            const int col = n0 + wn * 64 + nj * 8 + tg * 2;
            float2 bv = *(const float2*)(bias + col);
            float c0x = acc[mi][nj][0] + bv.x;
            float c0y = acc[mi][nj][1] + bv.y;
            float c1x = acc[mi][nj][2] + bv.x;
            float c1y = acc[mi][nj][3] + bv.y;
            if (RELU) {
                c0x = fmaxf(c0x, 0.f); c0y = fmaxf(c0y, 0.f);
                c1x = fmaxf(c1x, 0.f); c1y = fmaxf(c1y, 0.f);
            }
            if (OMODE == 0) {
                float* C = (float*)Cv;
                float2 u; u.x = c0x; u.y = c0y;
                float2 w; w.x = c1x; w.y = c1y;
                *(float2*)(C + (size_t)row * N + col)       = u;
                *(float2*)(C + (size_t)(row + 8) * N + col) = w;
            } else {
                __half* C = (__half*)Cv;
                *(__half2*)(C + (size_t)row * N + col)       = __floats2half2_rn(c0x, c0y);
                *(__half2*)(C + (size_t)(row + 8) * N + col) = __floats2half2_rn(c1x, c1y);
            }
        }
    }
}

// ---------------------------------------------------------------------------
// Fused QKV GEMM (round-12 config + .ca A loads): N=1536 regions q/k/vt.
// ---------------------------------------------------------------------------
struct QKVp {
    const __half* w[3];
    const float*  b[3];
    __half* q; __half* k; __half* vt;
};

__global__ void __launch_bounds__(128, 4) gemm_qkv(
    const __half* __restrict__ A, QKVp p, int M, int K)
{
    extern __shared__ __half smg[];
    const uint32_t aBase = smem_u32(smg);
    const uint32_t bBase = aBase + 2 * A_ST;

    const int tid  = threadIdx.x;
    const int warp = tid >> 5;
    const int lane = tid & 31;
    const int g    = lane >> 2;
    const int tg   = lane & 3;
    const int wm   = warp >> 1;
    const int wn   = warp & 1;
    const int m0   = blockIdx.y * 64;
    const int n0g  = blockIdx.x * 128;
    const int reg  = n0g >> 9;
    const int n0   = n0g & 511;
    const __half* W = p.w[reg];
    const float* bias = p.b[reg];

    float acc[2][8][4];
#pragma unroll
    for (int mi = 0; mi < 2; mi++)
#pragma unroll
        for (int nj = 0; nj < 8; nj++)
#pragma unroll
            for (int r = 0; r < 4; r++) acc[mi][nj][r] = 0.f;

    const int nt = K >> 6;

    auto issue = [&](int kt, int slot) {
        const int k0 = kt << 6;
        const uint32_t aOff = aBase + slot * A_ST;
        const uint32_t bOff = bBase + slot * B_ST;
#pragma unroll
        for (int t = 0; t < 4; t++) {
            const int ia = tid + t * 128;
            const int ra = ia >> 3, ca = ia & 7;
            CP_ASYNC16_CA(aOff + (uint32_t)(ra * AP2 * 2 + ca * 16),
                          A + (size_t)(m0 + ra) * K + k0 + ca * 8);
        }
#pragma unroll
        for (int t = 0; t < 8; t++) {
            const int ib = tid + t * 128;
            const int rb = ib >> 4, cb = ib & 15;
            CP_ASYNC16(bOff + (uint32_t)(rb * BPH * 2 + cb * 16),
                       W + (size_t)(k0 + rb) * 512 + n0 + cb * 8);
        }
        CP_COMMIT();
    };

    issue(0, 0);

    for (int kt = 0; kt < nt; kt++) {
        const int slot = kt & 1;
        CP_WAIT(0);
        __syncthreads();
        if (kt + 1 < nt) issue(kt + 1, slot ^ 1);

        const uint32_t aB = aBase + slot * A_ST;
        const uint32_t bB = bBase + slot * B_ST;
        const int lrow = lane & 15;
        const int lcol = (lane >> 4) << 3;

#pragma unroll
        for (int ks = 0; ks < 4; ks++) {
            const int kb = ks * 16;
            unsigned a[2][4];
#pragma unroll
            for (int mi = 0; mi < 2; mi++) {
                const int row0 = wm * 32 + mi * 16;
                ldm_x4(a[mi][0], a[mi][1], a[mi][2], a[mi][3],
                       aB + (uint32_t)(((row0 + lrow) * AP2 + kb + lcol) * 2));
            }
            unsigned b[8][2];
#pragma unroll
            for (int njp = 0; njp < 4; njp++) {
                const int col0 = wn * 64 + njp * 16;
                ldm_x4_t(b[2 * njp][0], b[2 * njp][1],
                         b[2 * njp + 1][0], b[2 * njp + 1][1],
                         bB + (uint32_t)(((kb + lrow) * BPH + col0 + lcol) * 2));
            }
#pragma unroll
            for (int mi = 0; mi < 2; mi++)
#pragma unroll
                for (int nj = 0; nj < 8; nj++)
                    mma_f16(acc[mi][nj][0], acc[mi][nj][1],
                            acc[mi][nj][2], acc[mi][nj][3],
                            a[mi][0], a[mi][1], a[mi][2], a[mi][3],
                            b[nj][0], b[nj][1]);
        }
    }

#pragma unroll
    for (int mi = 0; mi < 2; mi++) {
        const int row = m0 + wm * 32 + mi * 16 + g;
#pragma unroll
        for (int nj = 0; nj < 8; nj++) {
            const int coln = n0 + wn * 64 + nj * 8 + tg * 2;
            float2 bv = *(const float2*)(bias + coln);
            const float c0x = acc[mi][nj][0] + bv.x;
            const float c0y = acc[mi][nj][1] + bv.y;
            const float c1x = acc[mi][nj][2] + bv.x;
            const float c1y = acc[mi][nj][3] + bv.y;
            if (reg == 2) {
                __half* C = p.vt;
                const int b = row >> 11, s = row & 2047;
                const int h = coln >> 6, dd = coln & 63;
                const size_t base = (((size_t)(b * 8 + h) * 64 + dd) << 11);
                C[base + s]            = __float2half_rn(c0x);
                C[base + 2048 + s]     = __float2half_rn(c0y);
                C[base + s + 8]        = __float2half_rn(c1x);
                C[base + 2048 + s + 8] = __float2half_rn(c1y);
            } else {
                __half* C = (reg == 0) ? p.q : p.k;
                *(__half2*)(C + (size_t)row * DMODEL + coln)       = __floats2half2_rn(c0x, c0y);
                *(__half2*)(C + (size_t)(row + 8) * DMODEL + coln) = __floats2half2_rn(c1x, c1y);
            }
        }
    }
}

// ---------------------------------------------------------------------------
// FP16 flash attention (round-12 config): QTILE=256, register-resident P,
// cp.async pipeline, single barrier per kt, exp2 softmax.
// ---------------------------------------------------------------------------
#define QP_STRIDE 72
#define QTILE 256
#define KVBUF (64 * QP_STRIDE)

__global__ __launch_bounds__(256) void attn_f16(
    const __half* __restrict__ Qg, const __half* __restrict__ Kg,
    const __half* __restrict__ Vt, __half* __restrict__ Og)
{
    extern __shared__ __half smh[];
    __half (*QP)[QP_STRIDE] = (__half(*)[QP_STRIDE])smh;
    __half* KsBase = smh + QTILE * QP_STRIDE;
    __half* VsBase = KsBase + 2 * KVBUF;

    const int tid  = threadIdx.x;
    const int warp = tid >> 5;
    const int lane = tid & 31;
    const int g    = lane >> 2;
    const int tg   = lane & 3;
    const int bh   = blockIdx.y;
    const int b    = bh >> 3;
    const int h    = bh & 7;
    const int q0   = blockIdx.x * QTILE;
    const int wrow = warp * 32;

    const uint32_t qpB = smem_u32(&QP[0][0]);
    const uint32_t ksB = smem_u32(KsBase);
    const uint32_t vsB = smem_u32(VsBase);
    const int lr16 = lane & 15;
    const int lc16 = (lane >> 4) << 3;
    const int lr8  = (lane & 7) + ((lane >> 4) << 3);
    const int lc8  = ((lane >> 3) & 1) << 3;

    const __half* Qb  = Qg + (size_t)b * SQ * DMODEL + h * HDIM;
    const __half* Kb  = Kg + (size_t)b * SQ * DMODEL + h * HDIM;
    const __half* Vtb = Vt + (size_t)bh * HDIM * SQ;

    const __half2 sc = __float2half2_rn(0.125f * 1.4426950408889634f);
#pragma unroll
    for (int t = 0; t < 8; t++) {
        const int idx = tid + t * 256;
        const int r = idx >> 3, c = (idx & 7) * 8;
        uint4 v = *(const uint4*)(Qb + (size_t)(q0 + r) * DMODEL + c);
        __half2* pv = (__half2*)&v;
#pragma unroll
        for (int j = 0; j < 4; j++) pv[j] = __hmul2(pv[j], sc);
        *(uint4*)&QP[r][c] = v;
    }

#pragma unroll
    for (int t = 0; t < 2; t++) {
        const int idx = tid + t * 256;
        const int r = idx >> 3, c = (idx & 7) * 8;
        CP_ASYNC16(ksB + (uint32_t)((r * QP_STRIDE + c) * 2),
                   Kb + (size_t)r * DMODEL + c);
        CP_ASYNC16(vsB + (uint32_t)((r * QP_STRIDE + c) * 2),
                   Vtb + (size_t)r * SQ + c);
    }
    CP_COMMIT();
    __syncthreads();

    unsigned qf[4][2][4];
#pragma unroll
    for (int ks = 0; ks < 4; ks++) {
        const int kb = ks * 16;
#pragma unroll
        for (int mi = 0; mi < 2; mi++) {
            const int row0 = wrow + mi * 16;
            ldm_x4(qf[ks][mi][0], qf[ks][mi][1], qf[ks][mi][2], qf[ks][mi][3],
                   qpB + (uint32_t)(((row0 + lr16) * QP_STRIDE + kb + lc16) * 2));
        }
    }

    float oacc[2][8][4];
#pragma unroll
    for (int mi = 0; mi < 2; mi++)
#pragma unroll
        for (int nj = 0; nj < 8; nj++)
#pragma unroll
            for (int r = 0; r < 4; r++) oacc[mi][nj][r] = 0.f;
    float mrow[2][2], lrow[2][2];
#pragma unroll
    for (int mi = 0; mi < 2; mi++) {
        mrow[mi][0] = mrow[mi][1] = -1e30f;
        lrow[mi][0] = lrow[mi][1] = 0.f;
    }

    const int NT = SQ / 64;
    for (int kt = 0; kt < NT; kt++) {
        const int k0 = kt * 64;
        const int buf = kt & 1;

        CP_WAIT(0);
        __syncthreads();

        if (kt + 1 < NT) {
            const int kn = (kt + 1) * 64;
            const uint32_t kOff = ksB + (buf ^ 1) * KVBUF * 2;
            const uint32_t vOff = vsB + (buf ^ 1) * KVBUF * 2;
#pragma unroll
            for (int t = 0; t < 2; t++) {
                const int idx = tid + t * 256;
                const int r = idx >> 3, c = (idx & 7) * 8;
                CP_ASYNC16(kOff + (uint32_t)((r * QP_STRIDE + c) * 2),
                           Kb + (size_t)(kn + r) * DMODEL + c);
                CP_ASYNC16(vOff + (uint32_t)((r * QP_STRIDE + c) * 2),
                           Vtb + (size_t)r * SQ + kn + c);
            }
            CP_COMMIT();
        }

        const uint32_t kB = ksB + buf * KVBUF * 2;
        const uint32_t vB = vsB + buf * KVBUF * 2;

        float sfrag[2][8][4];
#pragma unroll
        for (int mi = 0; mi < 2; mi++)
#pragma unroll
            for (int nj = 0; nj < 8; nj++)
#pragma unroll
                for (int r = 0; r < 4; r++) sfrag[mi][nj][r] = 0.f;

#pragma unroll
        for (int ks = 0; ks < 4; ks++) {
            const int kb = ks * 16;
            unsigned bq[8][2];
#pragma unroll
            for (int njp = 0; njp < 4; njp++) {
                ldm_x4(bq[2 * njp][0], bq[2 * njp][1],
                       bq[2 * njp + 1][0], bq[2 * njp + 1][1],
                       kB + (uint32_t)(((njp * 16 + lr8) * QP_STRIDE + kb + lc8) * 2));
            }
#pragma unroll
            for (int mi = 0; mi < 2; mi++)
#pragma unroll
                for (int nj = 0; nj < 8; nj++)
                    mma_f16(sfrag[mi][nj][0], sfrag[mi][nj][1],
                            sfrag[mi][nj][2], sfrag[mi][nj][3],
                            qf[ks][mi][0], qf[ks][mi][1],
                            qf[ks][mi][2], qf[ks][mi][3],
                            bq[nj][0], bq[nj][1]);
        }

        const bool need_mask = (k0 <= q0 + QTILE - 1 + WIN) && (k0 + 63 >= q0 - WIN);
        if (need_mask) {
#pragma unroll
            for (int mi = 0; mi < 2; mi++) {
                const int qr0 = q0 + wrow + mi * 16 + g;
                const int qr1 = qr0 + 8;
#pragma unroll
                for (int nj = 0; nj < 8; nj++) {
                    const int kc0 = k0 + nj * 8 + tg * 2;
                    if ((unsigned)(qr0 - kc0     + WIN) <= 2 * WIN) sfrag[mi][nj][0] = -1e9f;
                    if ((unsigned)(qr0 - kc0 - 1 + WIN) <= 2 * WIN) sfrag[mi][nj][1] = -1e9f;
                    if ((unsigned)(qr1 - kc0     + WIN) <= 2 * WIN) sfrag[mi][nj][2] = -1e9f;
                    if ((unsigned)(qr1 - kc0 - 1 + WIN) <= 2 * WIN) sfrag[mi][nj][3] = -1e9f;
                }
            }
        }

        unsigned pf[2][8][2];
#pragma unroll
        for (int mi = 0; mi < 2; mi++) {
            float tmax0 = -1e30f, tmax1 = -1e30f;
#pragma unroll
            for (int nj = 0; nj < 8; nj++) {
                tmax0 = fmaxf(tmax0, fmaxf(sfrag[mi][nj][0], sfrag[mi][nj][1]));
                tmax1 = fmaxf(tmax1, fmaxf(sfrag[mi][nj][2], sfrag[mi][nj][3]));
            }
#pragma unroll
            for (int off = 1; off <= 2; off <<= 1) {
                tmax0 = fmaxf(tmax0, __shfl_xor_sync(0xffffffffu, tmax0, off));
                tmax1 = fmaxf(tmax1, __shfl_xor_sync(0xffffffffu, tmax1, off));
            }
            const float mnew0 = fmaxf(mrow[mi][0], tmax0);
            const float mnew1 = fmaxf(mrow[mi][1], tmax1);
            const float alpha0 = exp2f(mrow[mi][0] - mnew0);
            const float alpha1 = exp2f(mrow[mi][1] - mnew1);

            float rs0 = 0.f, rs1 = 0.f;
#pragma unroll
            for (int nj = 0; nj < 8; nj++) {
                const float p0 = exp2f(sfrag[mi][nj][0] - mnew0);
                const float p1 = exp2f(sfrag[mi][nj][1] - mnew0);
                const float p2 = exp2f(sfrag[mi][nj][2] - mnew1);
                const float p3 = exp2f(sfrag[mi][nj][3] - mnew1);
                rs0 += p0 + p1;
                rs1 += p2 + p3;
                pf[mi][nj][0] = h2u(__floats2half2_rn(p0, p1));
                pf[mi][nj][1] = h2u(__floats2half2_rn(p2, p3));
            }
#pragma unroll
            for (int off = 1; off <= 2; off <<= 1) {
                rs0 += __shfl_xor_sync(0xffffffffu, rs0, off);
                rs1 += __shfl_xor_sync(0xffffffffu, rs1, off);
            }
            lrow[mi][0] = lrow[mi][0] * alpha0 + rs0;
            lrow[mi][1] = lrow[mi][1] * alpha1 + rs1;
            mrow[mi][0] = mnew0;
            mrow[mi][1] = mnew1;
#pragma unroll
            for (int nj = 0; nj < 8; nj++) {
                oacc[mi][nj][0] *= alpha0; oacc[mi][nj][1] *= alpha0;
                oacc[mi][nj][2] *= alpha1; oacc[mi][nj][3] *= alpha1;
            }
        }

#pragma unroll
        for (int ks = 0; ks < 4; ks++) {
            const int kb = ks * 16;
            unsigned bv[8][2];
#pragma unroll
            for (int njp = 0; njp < 4; njp++) {
                ldm_x4(bv[2 * njp][0], bv[2 * njp][1],
                       bv[2 * njp + 1][0], bv[2 * njp + 1][1],
                       vB + (uint32_t)(((njp * 16 + lr8) * QP_STRIDE + kb + lc8) * 2));
            }
#pragma unroll
            for (int mi = 0; mi < 2; mi++) {
                const unsigned a0 = pf[mi][2 * ks][0];
                const unsigned a1 = pf[mi][2 * ks][1];
                const unsigned a2 = pf[mi][2 * ks + 1][0];
                const unsigned a3 = pf[mi][2 * ks + 1][1];
#pragma unroll
                for (int nj = 0; nj < 8; nj++)
                    mma_f16(oacc[mi][nj][0], oacc[mi][nj][1],
                            oacc[mi][nj][2], oacc[mi][nj][3],
                            a0, a1, a2, a3, bv[nj][0], bv[nj][1]);
            }
        }
    }

    __half* Ob = Og + (size_t)b * SQ * DMODEL + h * HDIM;
#pragma unroll
    for (int mi = 0; mi < 2; mi++) {
        const float inv0 = 1.0f / lrow[mi][0];
        const float inv1 = 1.0f / lrow[mi][1];
        const int row0 = q0 + wrow + mi * 16 + g;
#pragma unroll
        for (int nj = 0; nj < 8; nj++) {
            const int col = nj * 8 + tg * 2;
            *(__half2*)(Ob + (size_t)row0 * DMODEL + col) =
                __floats2half2_rn(oacc[mi][nj][0] * inv0, oacc[mi][nj][1] * inv0);
            *(__half2*)(Ob + (size_t)(row0 + 8) * DMODEL + col) =
                __floats2half2_rn(oacc[mi][nj][2] * inv1, oacc[mi][nj][3] * inv1);
        }
    }
}

// ---------------------------------------------------------------------------
// Launch
// ---------------------------------------------------------------------------
extern "C" void kernel_launch(void* const* d_in, const int* in_sizes, int n_in,
                              void* d_out, int out_size)
{
    (void)in_sizes; (void)n_in; (void)out_size;

    const float* x  = (const float*)d_in[0];
    const float* W1 = (const float*)d_in[1];
    const float* b1 = (const float*)d_in[2];
    const float* W2 = (const float*)d_in[3];
    const float* b2 = (const float*)d_in[4];
    const float* Wq = (const float*)d_in[5];
    const float* bq = (const float*)d_in[6];
    const float* Wk = (const float*)d_in[7];
    const float* bk = (const float*)d_in[8];
    const float* Wv = (const float*)d_in[9];
    const float* bv = (const float*)d_in[10];
    const float* Wo = (const float*)d_in[11];
    const float* bo = (const float*)d_in[12];
    float* out = (float*)d_out;

    __half *xh, *h1, *xm, *q, *k, *vt, *o;
    __half *w1h, *w2h, *wqh, *wkh, *wvh, *woh;
    cudaGetSymbolAddress((void**)&xh, g_xh);
    cudaGetSymbolAddress((void**)&h1, g_h1);
    cudaGetSymbolAddress((void**)&xm, g_xm);
    cudaGetSymbolAddress((void**)&q,  g_q);
    cudaGetSymbolAddress((void**)&k,  g_k);
    cudaGetSymbolAddress((void**)&vt, g_vt);
    cudaGetSymbolAddress((void**)&o,  g_o);
    cudaGetSymbolAddress((void**)&w1h, g_w1h);
    cudaGetSymbolAddress((void**)&w2h, g_w2h);
    cudaGetSymbolAddress((void**)&wqh, g_wqh);
    cudaGetSymbolAddress((void**)&wkh, g_wkh);
    cudaGetSymbolAddress((void**)&wvh, g_wvh);
    cudaGetSymbolAddress((void**)&woh, g_woh);

    cudaFuncSetAttribute(gemm_f16<1, 1>, cudaFuncAttributeMaxDynamicSharedMemorySize, GSMEM);
    cudaFuncSetAttribute(gemm_f16<0, 1>, cudaFuncAttributeMaxDynamicSharedMemorySize, GSMEM);
    cudaFuncSetAttribute(gemm_f16<0, 0>, cudaFuncAttributeMaxDynamicSharedMemorySize, GSMEM);
    cudaFuncSetAttribute(gemm_qkv, cudaFuncAttributeMaxDynamicSharedMemorySize, GSMEM);
    const int attn_smem = (QTILE * QP_STRIDE + 4 * KVBUF) * (int)sizeof(__half); // 73728
    cudaFuncSetAttribute(attn_f16, cudaFuncAttributeMaxDynamicSharedMemorySize,
                         attn_smem);

    // Fused prep
    Prep pr;
    pr.src[0] = x;  pr.dst[0] = xh;
    pr.src[1] = W1; pr.dst[1] = w1h;
    pr.src[2] = W2; pr.dst[2] = w2h;
    pr.src[3] = Wq; pr.dst[3] = wqh;
    pr.src[4] = Wk; pr.dst[4] = wkh;
    pr.src[5] = Wv; pr.dst[5] = wvh;
    pr.src[6] = Wo; pr.dst[6] = woh;
    const unsigned cnt[7] = {
        (TOK * DMODEL) / 4, (512 * 1024) / 4, (1024 * 512) / 4,
        (512 * 512) / 4, (512 * 512) / 4, (512 * 512) / 4, (512 * 512) / 4 };
    unsigned acc = 0;
    for (int i = 0; i < 7; i++) { pr.cum[i] = acc; acc += cnt[i]; }
    pr.cum[7] = acc;
    prep_all<<<(acc + 255) / 256, 256>>>(pr);

    QKVp qp;
    qp.w[0] = wqh; qp.w[1] = wkh; qp.w[2] = wvh;
    qp.b[0] = bq;  qp.b[1] = bk;  qp.b[2] = bv;
    qp.q = q; qp.k = k; qp.vt = vt;

    dim3 blk(128);
    gemm_f16<1, 1><<<dim3(1024 / 128, TOK / 64), blk, GSMEM>>>(xh, w1h, b1, h1, TOK, 1024, DMODEL);
    gemm_f16<0, 1><<<dim3(DMODEL / 128, TOK / 64), blk, GSMEM>>>(h1, w2h, b2, xm, TOK, DMODEL, 1024);
    gemm_qkv<<<dim3(1536 / 128, TOK / 64), blk, GSMEM>>>(xm, qp, TOK, DMODEL);
    attn_f16<<<dim3(SQ / QTILE, 4 * NHEADS), dim3(256), attn_smem>>>(q, k, vt, o);
    gemm_f16<0, 0><<<dim3(DMODEL / 128, TOK / 64), blk, GSMEM>>>(o, woh, bo, out, TOK, DMODEL, DMODEL);
}

// round 17
// speedup vs baseline: 1.0390x; 1.0135x over previous
#include <cuda_runtime.h>
#include <cuda_fp16.h>
#include <cstdint>

#define TOK    8192
#define DMODEL 512
#define SQ     2048
#define NHEADS 8
#define HDIM   64
#define WIN    5

// ---------------------------------------------------------------------------
// Device scratch (half). Weights in [K][N] layout.
// ---------------------------------------------------------------------------
__device__ __half g_xh[(size_t)TOK * DMODEL];
__device__ __half g_h1[(size_t)TOK * 1024];
__device__ __half g_xm[(size_t)TOK * DMODEL];
__device__ __half g_q [(size_t)TOK * DMODEL];
__device__ __half g_k [(size_t)TOK * DMODEL];
__device__ __half g_vt[(size_t)4 * NHEADS * HDIM * SQ];  // [b*8+h][d][s]
__device__ __half g_o [(size_t)TOK * DMODEL];
__device__ __half g_w1h[(size_t)512 * 1024];
__device__ __half g_w2h[(size_t)1024 * 512];
__device__ __half g_wqh[(size_t)512 * 512];
__device__ __half g_wkh[(size_t)512 * 512];
__device__ __half g_wvh[(size_t)512 * 512];
__device__ __half g_woh[(size_t)512 * 512];

// ---------------------------------------------------------------------------
// helpers
// ---------------------------------------------------------------------------
__device__ __forceinline__ uint32_t smem_u32(const void* p) {
    uint32_t a;
    asm("{ .reg .u64 t; cvta.to.shared.u64 t, %1; cvt.u32.u64 %0, t; }"
        : "=r"(a) : "l"(p));
    return a;
}

#define CP_ASYNC16(dst_u32, src_ptr) \
    asm volatile("cp.async.cg.shared.global [%0], [%1], 16;" \
                 :: "r"(dst_u32), "l"(src_ptr) : "memory")
#define CP_ASYNC16_CA(dst_u32, src_ptr) \
    asm volatile("cp.async.ca.shared.global [%0], [%1], 16;" \
                 :: "r"(dst_u32), "l"(src_ptr) : "memory")
#define CP_COMMIT() asm volatile("cp.async.commit_group;" ::: "memory")
#define CP_WAIT(n)  asm volatile("cp.async.wait_group %0;" :: "n"(n) : "memory")

__device__ __forceinline__ void mma_f16(
    float& d0, float& d1, float& d2, float& d3,
    unsigned a0, unsigned a1, unsigned a2, unsigned a3,
    unsigned b0, unsigned b1)
{
    asm volatile(
        "mma.sync.aligned.m16n8k16.row.col.f32.f16.f16.f32 "
        "{%0,%1,%2,%3},{%4,%5,%6,%7},{%8,%9},{%0,%1,%2,%3};\n"
        : "+f"(d0), "+f"(d1), "+f"(d2), "+f"(d3)
        : "r"(a0), "r"(a1), "r"(a2), "r"(a3), "r"(b0), "r"(b1));
}

__device__ __forceinline__ void ldm_x4(
    unsigned& r0, unsigned& r1, unsigned& r2, unsigned& r3, uint32_t addr)
{
    asm volatile("ldmatrix.sync.aligned.m8n8.x4.shared.b16 {%0,%1,%2,%3}, [%4];"
        : "=r"(r0), "=r"(r1), "=r"(r2), "=r"(r3) : "r"(addr));
}

__device__ __forceinline__ void ldm_x4_t(
    unsigned& r0, unsigned& r1, unsigned& r2, unsigned& r3, uint32_t addr)
{
    asm volatile("ldmatrix.sync.aligned.m8n8.x4.trans.shared.b16 {%0,%1,%2,%3}, [%4];"
        : "=r"(r0), "=r"(r1), "=r"(r2), "=r"(r3) : "r"(addr));
}

__device__ __forceinline__ unsigned h2u(__half2 h) {
    return *(unsigned*)&h;
}

// ---------------------------------------------------------------------------
// Fused prep: fp32 -> half for x + 6 weights in ONE launch.
// ---------------------------------------------------------------------------
struct Prep {
    const float* src[7];
    __half* dst[7];
    unsigned cum[8];
};

__global__ __launch_bounds__(256) void prep_all(Prep p)
{
    const unsigned i = blockIdx.x * 256 + threadIdx.x;
    if (i >= p.cum[7]) return;
    int s = 0;
#pragma unroll
    for (int j = 1; j < 7; j++) s += (i >= p.cum[j]) ? 1 : 0;
    const unsigned off = i - p.cum[s];
    float4 v = ((const float4*)p.src[s])[off];
    __half2* d = (__half2*)(p.dst[s] + (size_t)off * 4);
    d[0] = __floats2half2_rn(v.x, v.y);
    d[1] = __floats2half2_rn(v.z, v.w);
}

// ---------------------------------------------------------------------------
// FP16 GEMM: BM=64, BN=128, BK=64; 128 threads, 4 warps, warp tile 32x64,
// 2-stage cp.async, single barrier per k-iter. A via .ca, B via .cg.
// Load issue SPLIT across the ks loop (A before, B mid) to de-batch the
// LDGSTS burst and reduce cross-CTA L1tex queue contention.
// ---------------------------------------------------------------------------
#define AP2 72     // A row stride in halves (64+8)
#define BPH 136    // B row stride in halves (128+8)
#define A_ST (64 * AP2 * 2)          // 9216 B per A stage
#define B_ST (64 * BPH * 2)          // 17408 B per B stage
#define GSMEM (2 * (A_ST + B_ST))    // 53248

template<int RELU, int OMODE>
__global__ void __launch_bounds__(128, 4) gemm_f16(
    const __half* __restrict__ A, const __half* __restrict__ W,
    const float* __restrict__ bias, void* __restrict__ Cv,
    int M, int N, int K)
{
    extern __shared__ __half smg[];
    const uint32_t aBase = smem_u32(smg);
    const uint32_t bBase = aBase + 2 * A_ST;

    const int tid  = threadIdx.x;
    const int warp = tid >> 5;
    const int lane = tid & 31;
    const int g    = lane >> 2;
    const int tg   = lane & 3;
    const int wm   = warp >> 1;
    const int wn   = warp & 1;
    const int m0   = blockIdx.y * 64;
    const int n0   = blockIdx.x * 128;
    const int lrow = lane & 15;
    const int lcol = (lane >> 4) << 3;

    float acc[2][8][4];
#pragma unroll
    for (int mi = 0; mi < 2; mi++)
#pragma unroll
        for (int nj = 0; nj < 8; nj++)
#pragma unroll
            for (int r = 0; r < 4; r++) acc[mi][nj][r] = 0.f;

    const int nt = K >> 6;

    auto issueA = [&](int kt, int slot) {
        const int k0 = kt << 6;
        const uint32_t aOff = aBase + slot * A_ST;
#pragma unroll
        for (int t = 0; t < 4; t++) {
            const int ia = tid + t * 128;
            const int ra = ia >> 3, ca = ia & 7;
            CP_ASYNC16_CA(aOff + (uint32_t)(ra * AP2 * 2 + ca * 16),
                          A + (size_t)(m0 + ra) * K + k0 + ca * 8);
        }
    };
    auto issueB = [&](int kt, int slot) {
        const int k0 = kt << 6;
        const uint32_t bOff = bBase + slot * B_ST;
#pragma unroll
        for (int t = 0; t < 8; t++) {
            const int ib = tid + t * 128;
            const int rb = ib >> 4, cb = ib & 15;
            CP_ASYNC16(bOff + (uint32_t)(rb * BPH * 2 + cb * 16),
                       W + (size_t)(k0 + rb) * N + n0 + cb * 8);
        }
    };

    issueA(0, 0);
    issueB(0, 0);
    CP_COMMIT();

    for (int kt = 0; kt < nt; kt++) {
        const int slot = kt & 1;
        const bool more = (kt + 1 < nt);
        CP_WAIT(0);
        __syncthreads();
        if (more) issueA(kt + 1, slot ^ 1);

        const uint32_t aB = aBase + slot * A_ST;
        const uint32_t bB = bBase + slot * B_ST;

#pragma unroll
        for (int ks = 0; ks < 4; ks++) {
            const int kb = ks * 16;
            unsigned a[2][4];
#pragma unroll
            for (int mi = 0; mi < 2; mi++) {
                const int row0 = wm * 32 + mi * 16;
                ldm_x4(a[mi][0], a[mi][1], a[mi][2], a[mi][3],
                       aB + (uint32_t)(((row0 + lrow) * AP2 + kb + lcol) * 2));
            }
            unsigned b[8][2];
#pragma unroll
            for (int njp = 0; njp < 4; njp++) {
                const int col0 = wn * 64 + njp * 16;
                ldm_x4_t(b[2 * njp][0], b[2 * njp][1],
                         b[2 * njp + 1][0], b[2 * njp + 1][1],
                         bB + (uint32_t)(((kb + lrow) * BPH + col0 + lcol) * 2));
            }
#pragma unroll
            for (int mi = 0; mi < 2; mi++)
#pragma unroll
                for (int nj = 0; nj < 8; nj++)
                    mma_f16(acc[mi][nj][0], acc[mi][nj][1],
                            acc[mi][nj][2], acc[mi][nj][3],
                            a[mi][0], a[mi][1], a[mi][2], a[mi][3],
                            b[nj][0], b[nj][1]);

            if (ks == 1 && more) {
                issueB(kt + 1, slot ^ 1);
                CP_COMMIT();
            }
        }
    }

    // Epilogue
#pragma unroll
    for (int mi = 0; mi < 2; mi++) {
        const int row = m0 + wm * 32 + mi * 16 + g;
#pragma unroll
        for (int nj = 0; nj < 8; nj++) {
            const int col = n0 + wn * 64 + nj * 8 + tg * 2;
            float2 bv = *(const float2*)(bias + col);
            float c0x = acc[mi][nj][0] + bv.x;
            float c0y = acc[mi][nj][1] + bv.y;
            float c1x = acc[mi][nj][2] + bv.x;
            float c1y = acc[mi][nj][3] + bv.y;
            if (RELU) {
                c0x = fmaxf(c0x, 0.f); c0y = fmaxf(c0y, 0.f);
                c1x = fmaxf(c1x, 0.f); c1y = fmaxf(c1y, 0.f);
            }
            if (OMODE == 0) {
                float* C = (float*)Cv;
                float2 u; u.x = c0x; u.y = c0y;
                float2 w; w.x = c1x; w.y = c1y;
                *(float2*)(C + (size_t)row * N + col)       = u;
                *(float2*)(C + (size_t)(row + 8) * N + col) = w;
            } else {
                __half* C = (__half*)Cv;
                *(__half2*)(C + (size_t)row * N + col)       = __floats2half2_rn(c0x, c0y);
                *(__half2*)(C + (size_t)(row + 8) * N + col) = __floats2half2_rn(c1x, c1y);
            }
        }
    }
}

// ---------------------------------------------------------------------------
// Fused QKV GEMM (split-issue, .ca A loads): N=1536 regions q/k/vt.
// ---------------------------------------------------------------------------
struct QKVp {
    const __half* w[3];
    const float*  b[3];
    __half* q; __half* k; __half* vt;
};

__global__ void __launch_bounds__(128, 4) gemm_qkv(
    const __half* __restrict__ A, QKVp p, int M, int K)
{
    extern __shared__ __half smg[];
    const uint32_t aBase = smem_u32(smg);
    const uint32_t bBase = aBase + 2 * A_ST;

    const int tid  = threadIdx.x;
    const int warp = tid >> 5;
    const int lane = tid & 31;
    const int g    = lane >> 2;
    const int tg   = lane & 3;
    const int wm   = warp >> 1;
    const int wn   = warp & 1;
    const int m0   = blockIdx.y * 64;
    const int n0g  = blockIdx.x * 128;
    const int reg  = n0g >> 9;
    const int n0   = n0g & 511;
    const __half* W = p.w[reg];
    const float* bias = p.b[reg];
    const int lrow = lane & 15;
    const int lcol = (lane >> 4) << 3;

    float acc[2][8][4];
#pragma unroll
    for (int mi = 0; mi < 2; mi++)
#pragma unroll
        for (int nj = 0; nj < 8; nj++)
#pragma unroll
            for (int r = 0; r < 4; r++) acc[mi][nj][r] = 0.f;

    const int nt = K >> 6;

    auto issueA = [&](int kt, int slot) {
        const int k0 = kt << 6;
        const uint32_t aOff = aBase + slot * A_ST;
#pragma unroll
        for (int t = 0; t < 4; t++) {
            const int ia = tid + t * 128;
            const int ra = ia >> 3, ca = ia & 7;
            CP_ASYNC16_CA(aOff + (uint32_t)(ra * AP2 * 2 + ca * 16),
                          A + (size_t)(m0 + ra) * K + k0 + ca * 8);
        }
    };
    auto issueB = [&](int kt, int slot) {
        const int k0 = kt << 6;
        const uint32_t bOff = bBase + slot * B_ST;
#pragma unroll
        for (int t = 0; t < 8; t++) {
            const int ib = tid + t * 128;
            const int rb = ib >> 4, cb = ib & 15;
            CP_ASYNC16(bOff + (uint32_t)(rb * BPH * 2 + cb * 16),
                       W + (size_t)(k0 + rb) * 512 + n0 + cb * 8);
        }
    };

    issueA(0, 0);
    issueB(0, 0);
    CP_COMMIT();

    for (int kt = 0; kt < nt; kt++) {
        const int slot = kt & 1;
        const bool more = (kt + 1 < nt);
        CP_WAIT(0);
        __syncthreads();
        if (more) issueA(kt + 1, slot ^ 1);

        const uint32_t aB = aBase + slot * A_ST;
        const uint32_t bB = bBase + slot * B_ST;

#pragma unroll
        for (int ks = 0; ks < 4; ks++) {
            const int kb = ks * 16;
            unsigned a[2][4];
#pragma unroll
            for (int mi = 0; mi < 2; mi++) {
                const int row0 = wm * 32 + mi * 16;
                ldm_x4(a[mi][0], a[mi][1], a[mi][2], a[mi][3],
                       aB + (uint32_t)(((row0 + lrow) * AP2 + kb + lcol) * 2));
            }
            unsigned b[8][2];
#pragma unroll
            for (int njp = 0; njp < 4; njp++) {
                const int col0 = wn * 64 + njp * 16;
                ldm_x4_t(b[2 * njp][0], b[2 * njp][1],
                         b[2 * njp + 1][0], b[2 * njp + 1][1],
                         bB + (uint32_t)(((kb + lrow) * BPH + col0 + lcol) * 2));
            }
#pragma unroll
            for (int mi = 0; mi < 2; mi++)
#pragma unroll
                for (int nj = 0; nj < 8; nj++)
                    mma_f16(acc[mi][nj][0], acc[mi][nj][1],
                            acc[mi][nj][2], acc[mi][nj][3],
                            a[mi][0], a[mi][1], a[mi][2], a[mi][3],
                            b[nj][0], b[nj][1]);

            if (ks == 1 && more) {
                issueB(kt + 1, slot ^ 1);
                CP_COMMIT();
            }
        }
    }

#pragma unroll
    for (int mi = 0; mi < 2; mi++) {
        const int row = m0 + wm * 32 + mi * 16 + g;
#pragma unroll
        for (int nj = 0; nj < 8; nj++) {
            const int coln = n0 + wn * 64 + nj * 8 + tg * 2;
            float2 bv = *(const float2*)(bias + coln);
            const float c0x = acc[mi][nj][0] + bv.x;
            const float c0y = acc[mi][nj][1] + bv.y;
            const float c1x = acc[mi][nj][2] + bv.x;
            const float c1y = acc[mi][nj][3] + bv.y;
            if (reg == 2) {
                __half* C = p.vt;
                const int b = row >> 11, s = row & 2047;
                const int h = coln >> 6, dd = coln & 63;
                const size_t base = (((size_t)(b * 8 + h) * 64 + dd) << 11);
                C[base + s]            = __float2half_rn(c0x);
                C[base + 2048 + s]     = __float2half_rn(c0y);
                C[base + s + 8]        = __float2half_rn(c1x);
                C[base + 2048 + s + 8] = __float2half_rn(c1y);
            } else {
                __half* C = (reg == 0) ? p.q : p.k;
                *(__half2*)(C + (size_t)row * DMODEL + coln)       = __floats2half2_rn(c0x, c0y);
                *(__half2*)(C + (size_t)(row + 8) * DMODEL + coln) = __floats2half2_rn(c1x, c1y);
            }
        }
    }
}

// ---------------------------------------------------------------------------
// FP16 flash attention (round-12 config): QTILE=256, register-resident P,
// cp.async pipeline, single barrier per kt, exp2 softmax.
// ---------------------------------------------------------------------------
#define QP_STRIDE 72
#define QTILE 256
#define KVBUF (64 * QP_STRIDE)

__global__ __launch_bounds__(256) void attn_f16(
    const __half* __restrict__ Qg, const __half* __restrict__ Kg,
    const __half* __restrict__ Vt, __half* __restrict__ Og)
{
    extern __shared__ __half smh[];
    __half (*QP)[QP_STRIDE] = (__half(*)[QP_STRIDE])smh;
    __half* KsBase = smh + QTILE * QP_STRIDE;
    __half* VsBase = KsBase + 2 * KVBUF;

    const int tid  = threadIdx.x;
    const int warp = tid >> 5;
    const int lane = tid & 31;
    const int g    = lane >> 2;
    const int tg   = lane & 3;
    const int bh   = blockIdx.y;
    const int b    = bh >> 3;
    const int h    = bh & 7;
    const int q0   = blockIdx.x * QTILE;
    const int wrow = warp * 32;

    const uint32_t qpB = smem_u32(&QP[0][0]);
    const uint32_t ksB = smem_u32(KsBase);
    const uint32_t vsB = smem_u32(VsBase);
    const int lr16 = lane & 15;
    const int lc16 = (lane >> 4) << 3;
    const int lr8  = (lane & 7) + ((lane >> 4) << 3);
    const int lc8  = ((lane >> 3) & 1) << 3;

    const __half* Qb  = Qg + (size_t)b * SQ * DMODEL + h * HDIM;
    const __half* Kb  = Kg + (size_t)b * SQ * DMODEL + h * HDIM;
    const __half* Vtb = Vt + (size_t)bh * HDIM * SQ;

    const __half2 sc = __float2half2_rn(0.125f * 1.4426950408889634f);
#pragma unroll
    for (int t = 0; t < 8; t++) {
        const int idx = tid + t * 256;
        const int r = idx >> 3, c = (idx & 7) * 8;
        uint4 v = *(const uint4*)(Qb + (size_t)(q0 + r) * DMODEL + c);
        __half2* pv = (__half2*)&v;
#pragma unroll
        for (int j = 0; j < 4; j++) pv[j] = __hmul2(pv[j], sc);
        *(uint4*)&QP[r][c] = v;
    }

#pragma unroll
    for (int t = 0; t < 2; t++) {
        const int idx = tid + t * 256;
        const int r = idx >> 3, c = (idx & 7) * 8;
        CP_ASYNC16(ksB + (uint32_t)((r * QP_STRIDE + c) * 2),
                   Kb + (size_t)r * DMODEL + c);
        CP_ASYNC16(vsB + (uint32_t)((r * QP_STRIDE + c) * 2),
                   Vtb + (size_t)r * SQ + c);
    }
    CP_COMMIT();
    __syncthreads();

    unsigned qf[4][2][4];
#pragma unroll
    for (int ks = 0; ks < 4; ks++) {
        const int kb = ks * 16;
#pragma unroll
        for (int mi = 0; mi < 2; mi++) {
            const int row0 = wrow + mi * 16;
            ldm_x4(qf[ks][mi][0], qf[ks][mi][1], qf[ks][mi][2], qf[ks][mi][3],
                   qpB + (uint32_t)(((row0 + lr16) * QP_STRIDE + kb + lc16) * 2));
        }
    }

    float oacc[2][8][4];
#pragma unroll
    for (int mi = 0; mi < 2; mi++)
#pragma unroll
        for (int nj = 0; nj < 8; nj++)
#pragma unroll
            for (int r = 0; r < 4; r++) oacc[mi][nj][r] = 0.f;
    float mrow[2][2], lrow[2][2];
#pragma unroll
    for (int mi = 0; mi < 2; mi++) {
        mrow[mi][0] = mrow[mi][1] = -1e30f;
        lrow[mi][0] = lrow[mi][1] = 0.f;
    }

    const int NT = SQ / 64;
    for (int kt = 0; kt < NT; kt++) {
        const int k0 = kt * 64;
        const int buf = kt & 1;

        CP_WAIT(0);
        __syncthreads();

        if (kt + 1 < NT) {
            const int kn = (kt + 1) * 64;
            const uint32_t kOff = ksB + (buf ^ 1) * KVBUF * 2;
            const uint32_t vOff = vsB + (buf ^ 1) * KVBUF * 2;
#pragma unroll
            for (int t = 0; t < 2; t++) {
                const int idx = tid + t * 256;
                const int r = idx >> 3, c = (idx & 7) * 8;
                CP_ASYNC16(kOff + (uint32_t)((r * QP_STRIDE + c) * 2),
                           Kb + (size_t)(kn + r) * DMODEL + c);
                CP_ASYNC16(vOff + (uint32_t)((r * QP_STRIDE + c) * 2),
                           Vtb + (size_t)r * SQ + kn + c);
            }
            CP_COMMIT();
        }

        const uint32_t kB = ksB + buf * KVBUF * 2;
        const uint32_t vB = vsB + buf * KVBUF * 2;

        float sfrag[2][8][4];
#pragma unroll
        for (int mi = 0; mi < 2; mi++)
#pragma unroll
            for (int nj = 0; nj < 8; nj++)
#pragma unroll
                for (int r = 0; r < 4; r++) sfrag[mi][nj][r] = 0.f;

#pragma unroll
        for (int ks = 0; ks < 4; ks++) {
            const int kb = ks * 16;
            unsigned bq[8][2];
#pragma unroll
            for (int njp = 0; njp < 4; njp++) {
                ldm_x4(bq[2 * njp][0], bq[2 * njp][1],
                       bq[2 * njp + 1][0], bq[2 * njp + 1][1],
                       kB + (uint32_t)(((njp * 16 + lr8) * QP_STRIDE + kb + lc8) * 2));
            }
#pragma unroll
            for (int mi = 0; mi < 2; mi++)
#pragma unroll
                for (int nj = 0; nj < 8; nj++)
                    mma_f16(sfrag[mi][nj][0], sfrag[mi][nj][1],
                            sfrag[mi][nj][2], sfrag[mi][nj][3],
                            qf[ks][mi][0], qf[ks][mi][1],
                            qf[ks][mi][2], qf[ks][mi][3],
                            bq[nj][0], bq[nj][1]);
        }

        const bool need_mask = (k0 <= q0 + QTILE - 1 + WIN) && (k0 + 63 >= q0 - WIN);
        if (need_mask) {
#pragma unroll
            for (int mi = 0; mi < 2; mi++) {
                const int qr0 = q0 + wrow + mi * 16 + g;
                const int qr1 = qr0 + 8;
#pragma unroll
                for (int nj = 0; nj < 8; nj++) {
                    const int kc0 = k0 + nj * 8 + tg * 2;
                    if ((unsigned)(qr0 - kc0     + WIN) <= 2 * WIN) sfrag[mi][nj][0] = -1e9f;
                    if ((unsigned)(qr0 - kc0 - 1 + WIN) <= 2 * WIN) sfrag[mi][nj][1] = -1e9f;
                    if ((unsigned)(qr1 - kc0     + WIN) <= 2 * WIN) sfrag[mi][nj][2] = -1e9f;
                    if ((unsigned)(qr1 - kc0 - 1 + WIN) <= 2 * WIN) sfrag[mi][nj][3] = -1e9f;
                }
            }
        }

        unsigned pf[2][8][2];
#pragma unroll
        for (int mi = 0; mi < 2; mi++) {
            float tmax0 = -1e30f, tmax1 = -1e30f;
#pragma unroll
            for (int nj = 0; nj < 8; nj++) {
                tmax0 = fmaxf(tmax0, fmaxf(sfrag[mi][nj][0], sfrag[mi][nj][1]));
                tmax1 = fmaxf(tmax1, fmaxf(sfrag[mi][nj][2], sfrag[mi][nj][3]));
            }
#pragma unroll
            for (int off = 1; off <= 2; off <<= 1) {
                tmax0 = fmaxf(tmax0, __shfl_xor_sync(0xffffffffu, tmax0, off));
                tmax1 = fmaxf(tmax1, __shfl_xor_sync(0xffffffffu, tmax1, off));
            }
            const float mnew0 = fmaxf(mrow[mi][0], tmax0);
            const float mnew1 = fmaxf(mrow[mi][1], tmax1);
            const float alpha0 = exp2f(mrow[mi][0] - mnew0);
            const float alpha1 = exp2f(mrow[mi][1] - mnew1);

            float rs0 = 0.f, rs1 = 0.f;
#pragma unroll
            for (int nj = 0; nj < 8; nj++) {
                const float p0 = exp2f(sfrag[mi][nj][0] - mnew0);
                const float p1 = exp2f(sfrag[mi][nj][1] - mnew0);
                const float p2 = exp2f(sfrag[mi][nj][2] - mnew1);
                const float p3 = exp2f(sfrag[mi][nj][3] - mnew1);
                rs0 += p0 + p1;
                rs1 += p2 + p3;
                pf[mi][nj][0] = h2u(__floats2half2_rn(p0, p1));
                pf[mi][nj][1] = h2u(__floats2half2_rn(p2, p3));
            }
#pragma unroll
            for (int off = 1; off <= 2; off <<= 1) {
                rs0 += __shfl_xor_sync(0xffffffffu, rs0, off);
                rs1 += __shfl_xor_sync(0xffffffffu, rs1, off);
            }
            lrow[mi][0] = lrow[mi][0] * alpha0 + rs0;
            lrow[mi][1] = lrow[mi][1] * alpha1 + rs1;
            mrow[mi][0] = mnew0;
            mrow[mi][1] = mnew1;
#pragma unroll
            for (int nj = 0; nj < 8; nj++) {
                oacc[mi][nj][0] *= alpha0; oacc[mi][nj][1] *= alpha0;
                oacc[mi][nj][2] *= alpha1; oacc[mi][nj][3] *= alpha1;
            }
        }

#pragma unroll
        for (int ks = 0; ks < 4; ks++) {
            const int kb = ks * 16;
            unsigned bv[8][2];
#pragma unroll
            for (int njp = 0; njp < 4; njp++) {
                ldm_x4(bv[2 * njp][0], bv[2 * njp][1],
                       bv[2 * njp + 1][0], bv[2 * njp + 1][1],
                       vB + (uint32_t)(((njp * 16 + lr8) * QP_STRIDE + kb + lc8) * 2));
            }
#pragma unroll
            for (int mi = 0; mi < 2; mi++) {
                const unsigned a0 = pf[mi][2 * ks][0];
                const unsigned a1 = pf[mi][2 * ks][1];
                const unsigned a2 = pf[mi][2 * ks + 1][0];
                const unsigned a3 = pf[mi][2 * ks + 1][1];
#pragma unroll
                for (int nj = 0; nj < 8; nj++)
                    mma_f16(oacc[mi][nj][0], oacc[mi][nj][1],
                            oacc[mi][nj][2], oacc[mi][nj][3],
                            a0, a1, a2, a3, bv[nj][0], bv[nj][1]);
            }
        }
    }

    __half* Ob = Og + (size_t)b * SQ * DMODEL + h * HDIM;
#pragma unroll
    for (int mi = 0; mi < 2; mi++) {
        const float inv0 = 1.0f / lrow[mi][0];
        const float inv1 = 1.0f / lrow[mi][1];
        const int row0 = q0 + wrow + mi * 16 + g;
#pragma unroll
        for (int nj = 0; nj < 8; nj++) {
            const int col = nj * 8 + tg * 2;
            *(__half2*)(Ob + (size_t)row0 * DMODEL + col) =
                __floats2half2_rn(oacc[mi][nj][0] * inv0, oacc[mi][nj][1] * inv0);
            *(__half2*)(Ob + (size_t)(row0 + 8) * DMODEL + col) =
                __floats2half2_rn(oacc[mi][nj][2] * inv1, oacc[mi][nj][3] * inv1);
        }
    }
}

// ---------------------------------------------------------------------------
// Launch
// ---------------------------------------------------------------------------
extern "C" void kernel_launch(void* const* d_in, const int* in_sizes, int n_in,
                              void* d_out, int out_size)
{
    (void)in_sizes; (void)n_in; (void)out_size;

    const float* x  = (const float*)d_in[0];
    const float* W1 = (const float*)d_in[1];
    const float* b1 = (const float*)d_in[2];
    const float* W2 = (const float*)d_in[3];
    const float* b2 = (const float*)d_in[4];
    const float* Wq = (const float*)d_in[5];
    const float* bq = (const float*)d_in[6];
    const float* Wk = (const float*)d_in[7];
    const float* bk = (const float*)d_in[8];
    const float* Wv = (const float*)d_in[9];
    const float* bv = (const float*)d_in[10];
    const float* Wo = (const float*)d_in[11];
    const float* bo = (const float*)d_in[12];
    float* out = (float*)d_out;

    __half *xh, *h1, *xm, *q, *k, *vt, *o;
    __half *w1h, *w2h, *wqh, *wkh, *wvh, *woh;
    cudaGetSymbolAddress((void**)&xh, g_xh);
    cudaGetSymbolAddress((void**)&h1, g_h1);
    cudaGetSymbolAddress((void**)&xm, g_xm);
    cudaGetSymbolAddress((void**)&q,  g_q);
    cudaGetSymbolAddress((void**)&k,  g_k);
    cudaGetSymbolAddress((void**)&vt, g_vt);
    cudaGetSymbolAddress((void**)&o,  g_o);
    cudaGetSymbolAddress((void**)&w1h, g_w1h);
    cudaGetSymbolAddress((void**)&w2h, g_w2h);
    cudaGetSymbolAddress((void**)&wqh, g_wqh);
    cudaGetSymbolAddress((void**)&wkh, g_wkh);
    cudaGetSymbolAddress((void**)&wvh, g_wvh);
    cudaGetSymbolAddress((void**)&woh, g_woh);

    cudaFuncSetAttribute(gemm_f16<1, 1>, cudaFuncAttributeMaxDynamicSharedMemorySize, GSMEM);
    cudaFuncSetAttribute(gemm_f16<0, 1>, cudaFuncAttributeMaxDynamicSharedMemorySize, GSMEM);
    cudaFuncSetAttribute(gemm_f16<0, 0>, cudaFuncAttributeMaxDynamicSharedMemorySize, GSMEM);
    cudaFuncSetAttribute(gemm_qkv, cudaFuncAttributeMaxDynamicSharedMemorySize, GSMEM);
    const int attn_smem = (QTILE * QP_STRIDE + 4 * KVBUF) * (int)sizeof(__half); // 73728
    cudaFuncSetAttribute(attn_f16, cudaFuncAttributeMaxDynamicSharedMemorySize,
                         attn_smem);

    // Fused prep
    Prep pr;
    pr.src[0] = x;  pr.dst[0] = xh;
    pr.src[1] = W1; pr.dst[1] = w1h;
    pr.src[2] = W2; pr.dst[2] = w2h;
    pr.src[3] = Wq; pr.dst[3] = wqh;
    pr.src[4] = Wk; pr.dst[4] = wkh;
    pr.src[5] = Wv; pr.dst[5] = wvh;
    pr.src[6] = Wo; pr.dst[6] = woh;
    const unsigned cnt[7] = {
        (TOK * DMODEL) / 4, (512 * 1024) / 4, (1024 * 512) / 4,
        (512 * 512) / 4, (512 * 512) / 4, (512 * 512) / 4, (512 * 512) / 4 };
    unsigned acc = 0;
    for (int i = 0; i < 7; i++) { pr.cum[i] = acc; acc += cnt[i]; }
    pr.cum[7] = acc;
    prep_all<<<(acc + 255) / 256, 256>>>(pr);

    QKVp qp;
    qp.w[0] = wqh; qp.w[1] = wkh; qp.w[2] = wvh;
    qp.b[0] = bq;  qp.b[1] = bk;  qp.b[2] = bv;
    qp.q = q; qp.k = k; qp.vt = vt;

    dim3 blk(128);
    gemm_f16<1, 1><<<dim3(1024 / 128, TOK / 64), blk, GSMEM>>>(xh, w1h, b1, h1, TOK, 1024, DMODEL);
    gemm_f16<0, 1><<<dim3(DMODEL / 128, TOK / 64), blk, GSMEM>>>(h1, w2h, b2, xm, TOK, DMODEL, 1024);
    gemm_qkv<<<dim3(1536 / 128, TOK / 64), blk, GSMEM>>>(xm, qp, TOK, DMODEL);
    attn_f16<<<dim3(SQ / QTILE, 4 * NHEADS), dim3(256), attn_smem>>>(q, k, vt, o);
    gemm_f16<0, 0><<<dim3(DMODEL / 128, TOK / 64), blk, GSMEM>>>(o, woh, bo, out, TOK, DMODEL, DMODEL);
}